// round 1
// baseline (speedup 1.0000x reference)
#include <cuda_runtime.h>
#include <math.h>

#define BB   4
#define TSZ  256
#define DD   1024
#define HH   16
#define DHH  64
#define LL   4
#define VV   32000
#define FFD  4096
#define MM   767
#define MP   768
#define ROWS (BB*MP)   /* 3072 */

// ---------------- scratch (device globals, zero-initialized) ----------------
__device__ float g_x [ROWS*DD];
__device__ float g_h [ROWS*DD];
__device__ float g_q [ROWS*DD];
__device__ float g_k [ROWS*DD];
__device__ float g_v [ROWS*DD];
__device__ float g_y [ROWS*DD];
__device__ float g_ff[ROWS*FFD];

// ---------------- helpers ----------------
__device__ __forceinline__ float blk_sum(float v, float* sh) {
    int lane = threadIdx.x & 31, w = threadIdx.x >> 5;
#pragma unroll
    for (int o = 16; o; o >>= 1) v += __shfl_down_sync(0xffffffffu, v, o);
    if (lane == 0) sh[w] = v;
    __syncthreads();
    if (w == 0) {
        float t = (lane < (int)(blockDim.x >> 5)) ? sh[lane] : 0.f;
#pragma unroll
        for (int o = 16; o; o >>= 1) t += __shfl_down_sync(0xffffffffu, t, o);
        if (lane == 0) sh[0] = t;
    }
    __syncthreads();
    float r = sh[0];
    __syncthreads();
    return r;
}

// ---------------- embedding ----------------
__global__ void embed_kernel(const float* __restrict__ states,
                             const int*   __restrict__ actions,
                             const float* __restrict__ rtg,
                             const int*   __restrict__ timesteps,
                             const float* __restrict__ pos_emb,
                             const float* __restrict__ gpe,
                             const float* __restrict__ Ws, const float* __restrict__ bs,
                             const float* __restrict__ Wr, const float* __restrict__ br,
                             const float* __restrict__ aemb) {
    int m = blockIdx.x;   // 0..767
    int b = blockIdx.y;
    float* out = g_x + ((size_t)(b * MP + m)) * DD;
    if (m >= MM) {
        for (int d = threadIdx.x; d < DD; d += blockDim.x) out[d] = 0.f;
        return;
    }
    int ts = timesteps[b];
    int r = m % 3, t = m / 3;
    float sv = 0.f; int ai = 0;
    if (r == 0) sv = rtg[b * TSZ + t];
    else if (r == 1) sv = states[b * TSZ + t];
    else ai = actions[b * TSZ + t + 1];
    for (int d = threadIdx.x; d < DD; d += blockDim.x) {
        float tok;
        if (r == 0)      tok = tanhf(sv * Wr[d] + br[d]);
        else if (r == 1) tok = tanhf(sv * Ws[d] + bs[d]);
        else             tok = tanhf(aemb[(size_t)ai * DD + d]);
        out[d] = tok + gpe[(size_t)ts * DD + d] + pos_emb[(size_t)m * DD + d];
    }
}

// ---------------- layernorm (256 threads, D=1024) ----------------
__device__ __forceinline__ void ln_row(const float* __restrict__ xin,
                                       const float* __restrict__ g,
                                       const float* __restrict__ b,
                                       float* __restrict__ yout,
                                       float* red) {
    int t = threadIdx.x;
    float4 v = ((const float4*)xin)[t];
    float s  = v.x + v.y + v.z + v.w;
    float ss = v.x * v.x + v.y * v.y + v.z * v.z + v.w * v.w;
    float mean = blk_sum(s, red) * (1.f / DD);
    float var  = blk_sum(ss, red) * (1.f / DD) - mean * mean;
    float rs = rsqrtf(var + 1e-5f);
    float4 gg = ((const float4*)g)[t];
    float4 bb = ((const float4*)b)[t];
    float4 o;
    o.x = (v.x - mean) * rs * gg.x + bb.x;
    o.y = (v.y - mean) * rs * gg.y + bb.y;
    o.z = (v.z - mean) * rs * gg.z + bb.z;
    o.w = (v.w - mean) * rs * gg.w + bb.w;
    ((float4*)yout)[t] = o;
}

__global__ void ln_kernel(const float* __restrict__ in,
                          const float* __restrict__ g,
                          const float* __restrict__ b,
                          float* __restrict__ out) {
    __shared__ float red[32];
    size_t row = blockIdx.x;
    ln_row(in + row * DD, g, b, out + row * DD, red);
}

// gather state rows (m = 1+3t) and layernorm -> compact [B*256, D]
__global__ void gather_ln_kernel(const float* __restrict__ in,
                                 const float* __restrict__ g,
                                 const float* __restrict__ b,
                                 float* __restrict__ out) {
    __shared__ float red[32];
    int i = blockIdx.x;           // 0..1023
    int bb = i >> 8, t = i & 255;
    size_t row = (size_t)bb * MP + 1 + 3 * t;
    ln_row(in + row * DD, g, b, out + (size_t)i * DD, red);
}

// ---------------- GEMM: C[rows,N] = A[rows,K] @ W[N,K]^T (+bias, epilogue) ----------------
// EPI: 0=none, 1=gelu(exact), 2=+res
template <int EPI>
__global__ void __launch_bounds__(256)
gemm64_kernel(const float* __restrict__ A, const float* __restrict__ W,
              const float* __restrict__ bias, float* __restrict__ C,
              const float* __restrict__ res, int K, int N) {
    __shared__ float As[16][68];
    __shared__ float Bs[16][68];
    int tid = threadIdx.x;
    int tx = tid & 15, ty = tid >> 4;
    int rowBase = blockIdx.y * 64, colBase = blockIdx.x * 64;
    const float* Ab = A + (size_t)rowBase * K;
    const float* Wb = W + (size_t)colBase * K;
    int lm = tid >> 2;            // 0..63
    int lk = (tid & 3) * 4;       // 0,4,8,12
    float acc[4][4] = {};
    for (int k0 = 0; k0 < K; k0 += 16) {
        float4 a4 = *(const float4*)(Ab + (size_t)lm * K + k0 + lk);
        float4 b4 = *(const float4*)(Wb + (size_t)lm * K + k0 + lk);
        As[lk + 0][lm] = a4.x; As[lk + 1][lm] = a4.y; As[lk + 2][lm] = a4.z; As[lk + 3][lm] = a4.w;
        Bs[lk + 0][lm] = b4.x; Bs[lk + 1][lm] = b4.y; Bs[lk + 2][lm] = b4.z; Bs[lk + 3][lm] = b4.w;
        __syncthreads();
#pragma unroll
        for (int kk = 0; kk < 16; ++kk) {
            float4 av = *(const float4*)(&As[kk][ty * 4]);
            float4 bv = *(const float4*)(&Bs[kk][tx * 4]);
            acc[0][0] += av.x * bv.x; acc[0][1] += av.x * bv.y; acc[0][2] += av.x * bv.z; acc[0][3] += av.x * bv.w;
            acc[1][0] += av.y * bv.x; acc[1][1] += av.y * bv.y; acc[1][2] += av.y * bv.z; acc[1][3] += av.y * bv.w;
            acc[2][0] += av.z * bv.x; acc[2][1] += av.z * bv.y; acc[2][2] += av.z * bv.z; acc[2][3] += av.z * bv.w;
            acc[3][0] += av.w * bv.x; acc[3][1] += av.w * bv.y; acc[3][2] += av.w * bv.z; acc[3][3] += av.w * bv.w;
        }
        __syncthreads();
    }
    float bfr[4] = {0.f, 0.f, 0.f, 0.f};
    if (bias) {
#pragma unroll
        for (int j = 0; j < 4; j++) bfr[j] = bias[colBase + tx * 4 + j];
    }
#pragma unroll
    for (int i = 0; i < 4; i++) {
        size_t row = rowBase + ty * 4 + i;
        float* crow = C + row * N + colBase + tx * 4;
#pragma unroll
        for (int j = 0; j < 4; j++) {
            float c = acc[i][j] + bfr[j];
            if (EPI == 1) c = 0.5f * c * (1.f + erff(c * 0.70710678118654752f));
            else if (EPI == 2) c += res[row * N + colBase + tx * 4 + j];
            crow[j] = c;
        }
    }
}

// ---------------- causal attention: one block per (b,h,qm), 128 threads ----------------
__global__ void __launch_bounds__(128)
attn_kernel(const float* __restrict__ Q, const float* __restrict__ Kb,
            const float* __restrict__ Vb, float* __restrict__ Y) {
    int qm = blockIdx.x;                 // 0..766
    int bh = blockIdx.y;
    int b = bh / HH, h = bh % HH;
    __shared__ float sc[MP];
    __shared__ float qv[DHH];
    __shared__ float red[32];
    __shared__ float acc2[DHH];
    int tid = threadIdx.x, lane = tid & 31, w = tid >> 5;
    size_t base = (size_t)b * MP * DD + (size_t)h * DHH;
    if (tid < DHH) qv[tid] = Q[base + (size_t)qm * DD + tid];
    __syncthreads();
    int nk = qm + 1;
    // scores: each warp owns keys k = w, w+4, ...
    for (int k = w; k < nk; k += 4) {
        const float* kr = Kb + base + (size_t)k * DD;
        float d0 = kr[2 * lane] * qv[2 * lane] + kr[2 * lane + 1] * qv[2 * lane + 1];
#pragma unroll
        for (int o = 16; o; o >>= 1) d0 += __shfl_down_sync(0xffffffffu, d0, o);
        if (lane == 0) sc[k] = d0 * 0.125f;   // 1/sqrt(64)
    }
    __syncthreads();
    // block max
    float mx = -1e30f;
    for (int k = tid; k < nk; k += 128) mx = fmaxf(mx, sc[k]);
#pragma unroll
    for (int o = 16; o; o >>= 1) mx = fmaxf(mx, __shfl_down_sync(0xffffffffu, mx, o));
    if (lane == 0) red[w] = mx;
    __syncthreads();
    if (tid == 0) {
        float m2 = red[0];
        for (int i = 1; i < 4; i++) m2 = fmaxf(m2, red[i]);
        red[16] = m2;
    }
    __syncthreads();
    mx = red[16];
    __syncthreads();
    // exp + sum
    float s = 0.f;
    for (int k = tid; k < nk; k += 128) { float e = expf(sc[k] - mx); sc[k] = e; s += e; }
    s = blk_sum(s, red);
    float inv = 1.f / s;
    // weighted V: two k-strips, 64 dh lanes each
    int dh = tid & 63, strip = tid >> 6;
    float a = 0.f;
    for (int k = strip; k < nk; k += 2) a += sc[k] * Vb[base + (size_t)k * DD + dh];
    if (strip == 1) acc2[dh] = a;
    __syncthreads();
    if (strip == 0) Y[base + (size_t)qm * DD + dh] = (a + acc2[dh]) * inv;
}

// ---------------- launcher ----------------
extern "C" void kernel_launch(void* const* d_in, const int* in_sizes, int n_in,
                              void* d_out, int out_size) {
    const float* states  = (const float*)d_in[0];
    const int*   actions = (const int*)  d_in[1];
    const float* rtg     = (const float*)d_in[2];
    const int*   tsteps  = (const int*)  d_in[3];
    const float* pos_emb = (const float*)d_in[4];
    const float* gpe     = (const float*)d_in[5];
    const float* Ws      = (const float*)d_in[6];
    const float* bs      = (const float*)d_in[7];
    const float* Wr      = (const float*)d_in[8];
    const float* br      = (const float*)d_in[9];
    const float* aemb    = (const float*)d_in[10];
    const float* ln1_g   = (const float*)d_in[11];
    const float* ln1_b   = (const float*)d_in[12];
    const float* Wq      = (const float*)d_in[13];
    const float* bq      = (const float*)d_in[14];
    const float* Wk      = (const float*)d_in[15];
    const float* bk      = (const float*)d_in[16];
    const float* Wv      = (const float*)d_in[17];
    const float* bv      = (const float*)d_in[18];
    const float* Wo      = (const float*)d_in[19];
    const float* bo      = (const float*)d_in[20];
    const float* ln2_g   = (const float*)d_in[21];
    const float* ln2_b   = (const float*)d_in[22];
    const float* W1      = (const float*)d_in[23];
    const float* b1      = (const float*)d_in[24];
    const float* W2      = (const float*)d_in[25];
    const float* b2      = (const float*)d_in[26];
    const float* lnf_g   = (const float*)d_in[27];
    const float* lnf_b   = (const float*)d_in[28];
    const float* head_W  = (const float*)d_in[29];

    float *x, *hb, *qb, *kb, *vb, *yb, *ffb;
    cudaGetSymbolAddress((void**)&x,  g_x);
    cudaGetSymbolAddress((void**)&hb, g_h);
    cudaGetSymbolAddress((void**)&qb, g_q);
    cudaGetSymbolAddress((void**)&kb, g_k);
    cudaGetSymbolAddress((void**)&vb, g_v);
    cudaGetSymbolAddress((void**)&yb, g_y);
    cudaGetSymbolAddress((void**)&ffb, g_ff);

    embed_kernel<<<dim3(MP, BB), 256>>>(states, actions, rtg, tsteps,
                                        pos_emb, gpe, Ws, bs, Wr, br, aemb);

    for (int l = 0; l < LL; ++l) {
        size_t wOff = (size_t)l * DD * DD;
        size_t bOff = (size_t)l * DD;
        ln_kernel<<<ROWS, 256>>>(x, ln1_g + bOff, ln1_b + bOff, hb);
        gemm64_kernel<0><<<dim3(16, ROWS / 64), 256>>>(hb, Wq + wOff, bq + bOff, qb, nullptr, DD, DD);
        gemm64_kernel<0><<<dim3(16, ROWS / 64), 256>>>(hb, Wk + wOff, bk + bOff, kb, nullptr, DD, DD);
        gemm64_kernel<0><<<dim3(16, ROWS / 64), 256>>>(hb, Wv + wOff, bv + bOff, vb, nullptr, DD, DD);
        attn_kernel<<<dim3(MM, BB * HH), 128>>>(qb, kb, vb, yb);
        gemm64_kernel<2><<<dim3(16, ROWS / 64), 256>>>(yb, Wo + wOff, bo + bOff, x, x, DD, DD);
        ln_kernel<<<ROWS, 256>>>(x, ln2_g + bOff, ln2_b + bOff, hb);
        gemm64_kernel<1><<<dim3(FFD / 64, ROWS / 64), 256>>>(hb, W1 + (size_t)l * FFD * DD,
                                                             b1 + (size_t)l * FFD, ffb, nullptr, DD, FFD);
        gemm64_kernel<2><<<dim3(16, ROWS / 64), 256>>>(ffb, W2 + (size_t)l * DD * FFD,
                                                       b2 + bOff, x, x, FFD, DD);
    }

    gather_ln_kernel<<<BB * TSZ, 256>>>(x, lnf_g, lnf_b, hb);
    // head: rows = B*256 = 1024, N = 32000, K = 1024, no bias
    gemm64_kernel<0><<<dim3(VV / 64, (BB * TSZ) / 64), 256>>>(hb, head_W, nullptr,
                                                              (float*)d_out, nullptr, DD, VV);
}

// round 3
// speedup vs baseline: 1.9032x; 1.9032x over previous
#include <cuda_runtime.h>
#include <math.h>
#include <stdint.h>

#define BB   4
#define TSZ  256
#define DD   1024
#define HH   16
#define DHH  64
#define LL   4
#define VV   32000
#define FFD  4096
#define MM   767
#define MP   768
#define ROWS (BB*MP)   /* 3072 */

// GEMM tile params
#define BMT 128
#define BNT 128
#define BKT 16
#define SST 20   /* smem row stride in floats; (20*r+c)%32 distinct for frag pattern */

// ---------------- scratch (device globals) ----------------
__device__ float g_x [ROWS*DD];
__device__ float g_h [ROWS*DD];
__device__ float g_q [ROWS*DD];
__device__ float g_k [ROWS*DD];
__device__ float g_v [ROWS*DD];
__device__ float g_y [ROWS*DD];
__device__ float g_ff[ROWS*FFD];

// ---------------- helpers ----------------
__device__ __forceinline__ float blk_sum(float v, float* sh) {
    int lane = threadIdx.x & 31, w = threadIdx.x >> 5;
#pragma unroll
    for (int o = 16; o; o >>= 1) v += __shfl_down_sync(0xffffffffu, v, o);
    if (lane == 0) sh[w] = v;
    __syncthreads();
    if (w == 0) {
        float t = (lane < (int)(blockDim.x >> 5)) ? sh[lane] : 0.f;
#pragma unroll
        for (int o = 16; o; o >>= 1) t += __shfl_down_sync(0xffffffffu, t, o);
        if (lane == 0) sh[0] = t;
    }
    __syncthreads();
    float r = sh[0];
    __syncthreads();
    return r;
}

__device__ __forceinline__ uint32_t f2tf(float f) {
    uint32_t u;
    asm("cvt.rna.tf32.f32 %0, %1;" : "=r"(u) : "f"(f));
    return u;
}

__device__ __forceinline__ void mma_tf32(float* c, const uint32_t* a, const uint32_t* b) {
    asm volatile(
        "mma.sync.aligned.m16n8k8.row.col.f32.tf32.tf32.f32 "
        "{%0,%1,%2,%3},{%4,%5,%6,%7},{%8,%9},{%0,%1,%2,%3};"
        : "+f"(c[0]), "+f"(c[1]), "+f"(c[2]), "+f"(c[3])
        : "r"(a[0]), "r"(a[1]), "r"(a[2]), "r"(a[3]), "r"(b[0]), "r"(b[1]));
}

// ---------------- embedding ----------------
__global__ void embed_kernel(const float* __restrict__ states,
                             const int*   __restrict__ actions,
                             const float* __restrict__ rtg,
                             const int*   __restrict__ timesteps,
                             const float* __restrict__ pos_emb,
                             const float* __restrict__ gpe,
                             const float* __restrict__ Ws, const float* __restrict__ bs,
                             const float* __restrict__ Wr, const float* __restrict__ br,
                             const float* __restrict__ aemb) {
    int m = blockIdx.x;
    int b = blockIdx.y;
    float* out = g_x + ((size_t)(b * MP + m)) * DD;
    if (m >= MM) {
        for (int d = threadIdx.x; d < DD; d += blockDim.x) out[d] = 0.f;
        return;
    }
    int ts = timesteps[b];
    int r = m % 3, t = m / 3;
    float sv = 0.f; int ai = 0;
    if (r == 0) sv = rtg[b * TSZ + t];
    else if (r == 1) sv = states[b * TSZ + t];
    else ai = actions[b * TSZ + t + 1];
    for (int d = threadIdx.x; d < DD; d += blockDim.x) {
        float tok;
        if (r == 0)      tok = tanhf(sv * Wr[d] + br[d]);
        else if (r == 1) tok = tanhf(sv * Ws[d] + bs[d]);
        else             tok = tanhf(aemb[(size_t)ai * DD + d]);
        out[d] = tok + gpe[(size_t)ts * DD + d] + pos_emb[(size_t)m * DD + d];
    }
}

// ---------------- layernorm ----------------
__device__ __forceinline__ void ln_row(const float* __restrict__ xin,
                                       const float* __restrict__ g,
                                       const float* __restrict__ b,
                                       float* __restrict__ yout,
                                       float* red) {
    int t = threadIdx.x;
    float4 v = ((const float4*)xin)[t];
    float s  = v.x + v.y + v.z + v.w;
    float ss = v.x * v.x + v.y * v.y + v.z * v.z + v.w * v.w;
    float mean = blk_sum(s, red) * (1.f / DD);
    float var  = blk_sum(ss, red) * (1.f / DD) - mean * mean;
    float rs = rsqrtf(var + 1e-5f);
    float4 gg = ((const float4*)g)[t];
    float4 bb = ((const float4*)b)[t];
    float4 o;
    o.x = (v.x - mean) * rs * gg.x + bb.x;
    o.y = (v.y - mean) * rs * gg.y + bb.y;
    o.z = (v.z - mean) * rs * gg.z + bb.z;
    o.w = (v.w - mean) * rs * gg.w + bb.w;
    ((float4*)yout)[t] = o;
}

__global__ void ln_kernel(const float* __restrict__ in,
                          const float* __restrict__ g,
                          const float* __restrict__ b,
                          float* __restrict__ out) {
    __shared__ float red[32];
    size_t row = blockIdx.x;
    ln_row(in + row * DD, g, b, out + row * DD, red);
}

__global__ void gather_ln_kernel(const float* __restrict__ in,
                                 const float* __restrict__ g,
                                 const float* __restrict__ b,
                                 float* __restrict__ out) {
    __shared__ float red[32];
    int i = blockIdx.x;
    int bb = i >> 8, t = i & 255;
    size_t row = (size_t)bb * MP + 1 + 3 * t;
    ln_row(in + row * DD, g, b, out + (size_t)i * DD, red);
}

// ---------------- TF32 tensor-core GEMM body ----------------
// C[rows,N] = A[rows,K] @ W[N,K]^T (+bias, epilogue). EPI: 0=none, 1=gelu, 2=+res
template <int EPI>
__device__ __forceinline__ void gemm_body(const float* __restrict__ A,
                                          const float* __restrict__ W,
                                          const float* __restrict__ bias,
                                          float* __restrict__ C,
                                          const float* __restrict__ res,
                                          int K, int N, int bx, int by,
                                          uint32_t* As, uint32_t* Bs) {
    int tid  = threadIdx.x;
    int lane = tid & 31, warp = tid >> 5;
    int warpM = (warp & 1) * 64;
    int warpN = (warp >> 1) * 32;
    int rowBase = by * BMT, colBase = bx * BNT;
    const float* Ab = A + (size_t)rowBase * K;
    const float* Wb = W + (size_t)colBase * K;

    // global->smem mapping: 512 float4 per tile, thread handles idx tid, tid+256
    int r0 = tid >> 2,         kq = (tid & 3) * 4;
    int r1 = (tid + 256) >> 2; // same kq

    float4 a4[2], b4[2];

    float acc[4][4][4];
#pragma unroll
    for (int i = 0; i < 4; i++)
#pragma unroll
        for (int j = 0; j < 4; j++)
#pragma unroll
            for (int q = 0; q < 4; q++) acc[i][j][q] = 0.f;

    // prologue load
    a4[0] = *(const float4*)(Ab + (size_t)r0 * K + kq);
    a4[1] = *(const float4*)(Ab + (size_t)r1 * K + kq);
    b4[0] = *(const float4*)(Wb + (size_t)r0 * K + kq);
    b4[1] = *(const float4*)(Wb + (size_t)r1 * K + kq);
    {
        uint32_t* a = As; uint32_t* bsm = Bs;
        a[r0*SST+kq+0]=f2tf(a4[0].x); a[r0*SST+kq+1]=f2tf(a4[0].y);
        a[r0*SST+kq+2]=f2tf(a4[0].z); a[r0*SST+kq+3]=f2tf(a4[0].w);
        a[r1*SST+kq+0]=f2tf(a4[1].x); a[r1*SST+kq+1]=f2tf(a4[1].y);
        a[r1*SST+kq+2]=f2tf(a4[1].z); a[r1*SST+kq+3]=f2tf(a4[1].w);
        bsm[r0*SST+kq+0]=f2tf(b4[0].x); bsm[r0*SST+kq+1]=f2tf(b4[0].y);
        bsm[r0*SST+kq+2]=f2tf(b4[0].z); bsm[r0*SST+kq+3]=f2tf(b4[0].w);
        bsm[r1*SST+kq+0]=f2tf(b4[1].x); bsm[r1*SST+kq+1]=f2tf(b4[1].y);
        bsm[r1*SST+kq+2]=f2tf(b4[1].z); bsm[r1*SST+kq+3]=f2tf(b4[1].w);
    }
    __syncthreads();

    int nc = K / BKT;
    for (int c = 0; c < nc; ++c) {
        int buf = c & 1;
        if (c + 1 < nc) {
            int k0 = (c + 1) * BKT;
            a4[0] = *(const float4*)(Ab + (size_t)r0 * K + k0 + kq);
            a4[1] = *(const float4*)(Ab + (size_t)r1 * K + k0 + kq);
            b4[0] = *(const float4*)(Wb + (size_t)r0 * K + k0 + kq);
            b4[1] = *(const float4*)(Wb + (size_t)r1 * K + k0 + kq);
        }
        const uint32_t* as  = As + buf * (BMT * SST);
        const uint32_t* bsm = Bs + buf * (BNT * SST);
#pragma unroll
        for (int ks = 0; ks < 2; ++ks) {
            int kb = ks * 8 + (lane & 3);
            uint32_t af[4][4], bf[4][2];
#pragma unroll
            for (int mt = 0; mt < 4; ++mt) {
                int rr = warpM + mt * 16 + (lane >> 2);
                af[mt][0] = as[rr * SST + kb];
                af[mt][1] = as[(rr + 8) * SST + kb];
                af[mt][2] = as[rr * SST + kb + 4];
                af[mt][3] = as[(rr + 8) * SST + kb + 4];
            }
#pragma unroll
            for (int nt = 0; nt < 4; ++nt) {
                int cc = warpN + nt * 8 + (lane >> 2);
                bf[nt][0] = bsm[cc * SST + kb];
                bf[nt][1] = bsm[cc * SST + kb + 4];
            }
#pragma unroll
            for (int mt = 0; mt < 4; ++mt)
#pragma unroll
                for (int nt = 0; nt < 4; ++nt)
                    mma_tf32(acc[mt][nt], af[mt], bf[nt]);
        }
        if (c + 1 < nc) {
            uint32_t* a  = As + (buf ^ 1) * (BMT * SST);
            uint32_t* bb = Bs + (buf ^ 1) * (BNT * SST);
            a[r0*SST+kq+0]=f2tf(a4[0].x); a[r0*SST+kq+1]=f2tf(a4[0].y);
            a[r0*SST+kq+2]=f2tf(a4[0].z); a[r0*SST+kq+3]=f2tf(a4[0].w);
            a[r1*SST+kq+0]=f2tf(a4[1].x); a[r1*SST+kq+1]=f2tf(a4[1].y);
            a[r1*SST+kq+2]=f2tf(a4[1].z); a[r1*SST+kq+3]=f2tf(a4[1].w);
            bb[r0*SST+kq+0]=f2tf(b4[0].x); bb[r0*SST+kq+1]=f2tf(b4[0].y);
            bb[r0*SST+kq+2]=f2tf(b4[0].z); bb[r0*SST+kq+3]=f2tf(b4[0].w);
            bb[r1*SST+kq+0]=f2tf(b4[1].x); bb[r1*SST+kq+1]=f2tf(b4[1].y);
            bb[r1*SST+kq+2]=f2tf(b4[1].z); bb[r1*SST+kq+3]=f2tf(b4[1].w);
            __syncthreads();
        }
    }

    // epilogue
#pragma unroll
    for (int nt = 0; nt < 4; ++nt) {
        int col = colBase + warpN + nt * 8 + 2 * (lane & 3);
        float bv0 = 0.f, bv1 = 0.f;
        if (bias) { bv0 = bias[col]; bv1 = bias[col + 1]; }
#pragma unroll
        for (int mt = 0; mt < 4; ++mt) {
#pragma unroll
            for (int half = 0; half < 2; ++half) {
                int row = rowBase + warpM + mt * 16 + (lane >> 2) + half * 8;
                float v0 = acc[mt][nt][half * 2 + 0] + bv0;
                float v1 = acc[mt][nt][half * 2 + 1] + bv1;
                if (EPI == 1) {
                    v0 = 0.5f * v0 * (1.f + erff(v0 * 0.70710678118654752f));
                    v1 = 0.5f * v1 * (1.f + erff(v1 * 0.70710678118654752f));
                } else if (EPI == 2) {
                    const float* rr = res + (size_t)row * N + col;
                    v0 += rr[0]; v1 += rr[1];
                }
                float2 o = make_float2(v0, v1);
                *(float2*)(C + (size_t)row * N + col) = o;
            }
        }
    }
}

template <int EPI>
__global__ void __launch_bounds__(256)
gemm_tc(const float* __restrict__ A, const float* __restrict__ W,
        const float* __restrict__ bias, float* __restrict__ C,
        const float* __restrict__ res, int K, int N) {
    __shared__ uint32_t As[2 * BMT * SST];
    __shared__ uint32_t Bs[2 * BNT * SST];
    gemm_body<EPI>(A, W, bias, C, res, K, N, blockIdx.x, blockIdx.y, As, Bs);
}

// fused QKV: blockIdx.z selects projection
__global__ void __launch_bounds__(256)
qkv_tc(const float* __restrict__ A,
       const float* __restrict__ Wq, const float* __restrict__ bq, float* __restrict__ Cq,
       const float* __restrict__ Wk, const float* __restrict__ bk, float* __restrict__ Ck,
       const float* __restrict__ Wv, const float* __restrict__ bv, float* __restrict__ Cv) {
    __shared__ uint32_t As[2 * BMT * SST];
    __shared__ uint32_t Bs[2 * BNT * SST];
    const float* W; const float* bias; float* C;
    if (blockIdx.z == 0)      { W = Wq; bias = bq; C = Cq; }
    else if (blockIdx.z == 1) { W = Wk; bias = bk; C = Ck; }
    else                      { W = Wv; bias = bv; C = Cv; }
    gemm_body<0>(A, W, bias, C, nullptr, DD, DD, blockIdx.x, blockIdx.y, As, Bs);
}

// ---------------- causal attention ----------------
__global__ void __launch_bounds__(128)
attn_kernel(const float* __restrict__ Q, const float* __restrict__ Kb,
            const float* __restrict__ Vb, float* __restrict__ Y) {
    int qm = blockIdx.x;
    int bh = blockIdx.y;
    int b = bh / HH, h = bh % HH;
    __shared__ float sc[MP];
    __shared__ float qv[DHH];
    __shared__ float red[32];
    __shared__ float acc2[DHH];
    int tid = threadIdx.x, lane = tid & 31, w = tid >> 5;
    size_t base = (size_t)b * MP * DD + (size_t)h * DHH;
    if (tid < DHH) qv[tid] = Q[base + (size_t)qm * DD + tid];
    __syncthreads();
    int nk = qm + 1;
    for (int k = w; k < nk; k += 4) {
        const float* kr = Kb + base + (size_t)k * DD;
        float d0 = kr[2 * lane] * qv[2 * lane] + kr[2 * lane + 1] * qv[2 * lane + 1];
#pragma unroll
        for (int o = 16; o; o >>= 1) d0 += __shfl_down_sync(0xffffffffu, d0, o);
        if (lane == 0) sc[k] = d0 * 0.125f;
    }
    __syncthreads();
    float mx = -1e30f;
    for (int k = tid; k < nk; k += 128) mx = fmaxf(mx, sc[k]);
#pragma unroll
    for (int o = 16; o; o >>= 1) mx = fmaxf(mx, __shfl_down_sync(0xffffffffu, mx, o));
    if (lane == 0) red[w] = mx;
    __syncthreads();
    if (tid == 0) {
        float m2 = red[0];
        for (int i = 1; i < 4; i++) m2 = fmaxf(m2, red[i]);
        red[16] = m2;
    }
    __syncthreads();
    mx = red[16];
    __syncthreads();
    float s = 0.f;
    for (int k = tid; k < nk; k += 128) { float e = expf(sc[k] - mx); sc[k] = e; s += e; }
    s = blk_sum(s, red);
    float inv = 1.f / s;
    int dh = tid & 63, strip = tid >> 6;
    float a = 0.f;
    for (int k = strip; k < nk; k += 2) a += sc[k] * Vb[base + (size_t)k * DD + dh];
    if (strip == 1) acc2[dh] = a;
    __syncthreads();
    if (strip == 0) Y[base + (size_t)qm * DD + dh] = (a + acc2[dh]) * inv;
}

// ---------------- launcher ----------------
extern "C" void kernel_launch(void* const* d_in, const int* in_sizes, int n_in,
                              void* d_out, int out_size) {
    const float* states  = (const float*)d_in[0];
    const int*   actions = (const int*)  d_in[1];
    const float* rtg     = (const float*)d_in[2];
    const int*   tsteps  = (const int*)  d_in[3];
    const float* pos_emb = (const float*)d_in[4];
    const float* gpe     = (const float*)d_in[5];
    const float* Ws      = (const float*)d_in[6];
    const float* bs      = (const float*)d_in[7];
    const float* Wr      = (const float*)d_in[8];
    const float* br      = (const float*)d_in[9];
    const float* aemb    = (const float*)d_in[10];
    const float* ln1_g   = (const float*)d_in[11];
    const float* ln1_b   = (const float*)d_in[12];
    const float* Wq      = (const float*)d_in[13];
    const float* bq      = (const float*)d_in[14];
    const float* Wk      = (const float*)d_in[15];
    const float* bk      = (const float*)d_in[16];
    const float* Wv      = (const float*)d_in[17];
    const float* bv      = (const float*)d_in[18];
    const float* Wo      = (const float*)d_in[19];
    const float* bo      = (const float*)d_in[20];
    const float* ln2_g   = (const float*)d_in[21];
    const float* ln2_b   = (const float*)d_in[22];
    const float* W1      = (const float*)d_in[23];
    const float* b1      = (const float*)d_in[24];
    const float* W2      = (const float*)d_in[25];
    const float* b2      = (const float*)d_in[26];
    const float* lnf_g   = (const float*)d_in[27];
    const float* lnf_b   = (const float*)d_in[28];
    const float* head_W  = (const float*)d_in[29];

    float *x, *hb, *qb, *kb, *vb, *yb, *ffb;
    cudaGetSymbolAddress((void**)&x,  g_x);
    cudaGetSymbolAddress((void**)&hb, g_h);
    cudaGetSymbolAddress((void**)&qb, g_q);
    cudaGetSymbolAddress((void**)&kb, g_k);
    cudaGetSymbolAddress((void**)&vb, g_v);
    cudaGetSymbolAddress((void**)&yb, g_y);
    cudaGetSymbolAddress((void**)&ffb, g_ff);

    embed_kernel<<<dim3(MP, BB), 256>>>(states, actions, rtg, tsteps,
                                        pos_emb, gpe, Ws, bs, Wr, br, aemb);

    for (int l = 0; l < LL; ++l) {
        size_t wOff = (size_t)l * DD * DD;
        size_t bOff = (size_t)l * DD;
        ln_kernel<<<ROWS, 256>>>(x, ln1_g + bOff, ln1_b + bOff, hb);
        qkv_tc<<<dim3(DD / BNT, ROWS / BMT, 3), 256>>>(hb,
            Wq + wOff, bq + bOff, qb,
            Wk + wOff, bk + bOff, kb,
            Wv + wOff, bv + bOff, vb);
        attn_kernel<<<dim3(MM, BB * HH), 128>>>(qb, kb, vb, yb);
        gemm_tc<2><<<dim3(DD / BNT, ROWS / BMT), 256>>>(yb, Wo + wOff, bo + bOff, x, x, DD, DD);
        ln_kernel<<<ROWS, 256>>>(x, ln2_g + bOff, ln2_b + bOff, hb);
        gemm_tc<1><<<dim3(FFD / BNT, ROWS / BMT), 256>>>(hb, W1 + (size_t)l * FFD * DD,
                                                         b1 + (size_t)l * FFD, ffb, nullptr, DD, FFD);
        gemm_tc<2><<<dim3(DD / BNT, ROWS / BMT), 256>>>(ffb, W2 + (size_t)l * DD * FFD,
                                                        b2 + bOff, x, x, FFD, DD);
    }

    gather_ln_kernel<<<BB * TSZ, 256>>>(x, lnf_g, lnf_b, hb);
    gemm_tc<0><<<dim3(VV / BNT, (BB * TSZ) / BMT), 256>>>(hb, head_W, nullptr,
                                                          (float*)d_out, nullptr, DD, VV);
}

// round 5
// speedup vs baseline: 3.2647x; 1.7154x over previous
#include <cuda_runtime.h>
#include <math.h>
#include <stdint.h>

#define BB   4
#define TSZ  256
#define DD   1024
#define HH   16
#define DHH  64
#define LL   4
#define VV   32000
#define FFD  4096
#define MM   767
#define MP   768
#define ROWS (BB*MP)   /* 3072 */

// GEMM tile params
#define BMT 128
#define BNT 128
#define BKT 16
#define SST 20

// flash attention tile params
#define BQ  64
#define BK  64
#define AST 68
#define ATTN_SMEM (4 * BQ * AST * 4)

// ---------------- scratch (device globals) ----------------
__device__ float g_x [ROWS*DD];
__device__ float g_h [ROWS*DD];
__device__ float g_q [ROWS*DD];
__device__ float g_k [ROWS*DD];
__device__ float g_v [ROWS*DD];
__device__ float g_y [ROWS*DD];
__device__ float g_ff[ROWS*FFD];

// ---------------- helpers ----------------
__device__ __forceinline__ float blk_sum(float v, float* sh) {
    int lane = threadIdx.x & 31, w = threadIdx.x >> 5;
#pragma unroll
    for (int o = 16; o; o >>= 1) v += __shfl_down_sync(0xffffffffu, v, o);
    if (lane == 0) sh[w] = v;
    __syncthreads();
    if (w == 0) {
        float t = (lane < (int)(blockDim.x >> 5)) ? sh[lane] : 0.f;
#pragma unroll
        for (int o = 16; o; o >>= 1) t += __shfl_down_sync(0xffffffffu, t, o);
        if (lane == 0) sh[0] = t;
    }
    __syncthreads();
    float r = sh[0];
    __syncthreads();
    return r;
}

__device__ __forceinline__ uint32_t f2tf(float f) {
    uint32_t u;
    asm("cvt.rna.tf32.f32 %0, %1;" : "=r"(u) : "f"(f));
    return u;
}

__device__ __forceinline__ void mma_tf32(float* c, const uint32_t* a, const uint32_t* b) {
    asm volatile(
        "mma.sync.aligned.m16n8k8.row.col.f32.tf32.tf32.f32 "
        "{%0,%1,%2,%3},{%4,%5,%6,%7},{%8,%9},{%0,%1,%2,%3};"
        : "+f"(c[0]), "+f"(c[1]), "+f"(c[2]), "+f"(c[3])
        : "r"(a[0]), "r"(a[1]), "r"(a[2]), "r"(a[3]), "r"(b[0]), "r"(b[1]));
}

// ---------------- embedding ----------------
__global__ void embed_kernel(const float* __restrict__ states,
                             const int*   __restrict__ actions,
                             const float* __restrict__ rtg,
                             const int*   __restrict__ timesteps,
                             const float* __restrict__ pos_emb,
                             const float* __restrict__ gpe,
                             const float* __restrict__ Ws, const float* __restrict__ bs,
                             const float* __restrict__ Wr, const float* __restrict__ br,
                             const float* __restrict__ aemb) {
    int m = blockIdx.x;
    int b = blockIdx.y;
    float* out = g_x + ((size_t)(b * MP + m)) * DD;
    if (m >= MM) {
        for (int d = threadIdx.x; d < DD; d += blockDim.x) out[d] = 0.f;
        return;
    }
    int ts = timesteps[b];
    int r = m % 3, t = m / 3;
    float sv = 0.f; int ai = 0;
    if (r == 0) sv = rtg[b * TSZ + t];
    else if (r == 1) sv = states[b * TSZ + t];
    else ai = actions[b * TSZ + t + 1];
    for (int d = threadIdx.x; d < DD; d += blockDim.x) {
        float tok;
        if (r == 0)      tok = tanhf(sv * Wr[d] + br[d]);
        else if (r == 1) tok = tanhf(sv * Ws[d] + bs[d]);
        else             tok = tanhf(aemb[(size_t)ai * DD + d]);
        out[d] = tok + gpe[(size_t)ts * DD + d] + pos_emb[(size_t)m * DD + d];
    }
}

// ---------------- layernorm ----------------
__device__ __forceinline__ void ln_row(const float* __restrict__ xin,
                                       const float* __restrict__ g,
                                       const float* __restrict__ b,
                                       float* __restrict__ yout,
                                       float* red) {
    int t = threadIdx.x;
    float4 v = ((const float4*)xin)[t];
    float s  = v.x + v.y + v.z + v.w;
    float ss = v.x * v.x + v.y * v.y + v.z * v.z + v.w * v.w;
    float mean = blk_sum(s, red) * (1.f / DD);
    float var  = blk_sum(ss, red) * (1.f / DD) - mean * mean;
    float rs = rsqrtf(var + 1e-5f);
    float4 gg = ((const float4*)g)[t];
    float4 bb = ((const float4*)b)[t];
    float4 o;
    o.x = (v.x - mean) * rs * gg.x + bb.x;
    o.y = (v.y - mean) * rs * gg.y + bb.y;
    o.z = (v.z - mean) * rs * gg.z + bb.z;
    o.w = (v.w - mean) * rs * gg.w + bb.w;
    ((float4*)yout)[t] = o;
}

__global__ void ln_kernel(const float* __restrict__ in,
                          const float* __restrict__ g,
                          const float* __restrict__ b,
                          float* __restrict__ out) {
    __shared__ float red[32];
    size_t row = blockIdx.x;
    ln_row(in + row * DD, g, b, out + row * DD, red);
}

__global__ void gather_ln_kernel(const float* __restrict__ in,
                                 const float* __restrict__ g,
                                 const float* __restrict__ b,
                                 float* __restrict__ out) {
    __shared__ float red[32];
    int i = blockIdx.x;
    int bb = i >> 8, t = i & 255;
    size_t row = (size_t)bb * MP + 1 + 3 * t;
    ln_row(in + row * DD, g, b, out + (size_t)i * DD, red);
}

// ---------------- TF32 tensor-core GEMM ----------------
template <int EPI>
__device__ __forceinline__ void gemm_body(const float* __restrict__ A,
                                          const float* __restrict__ W,
                                          const float* __restrict__ bias,
                                          float* __restrict__ C,
                                          const float* __restrict__ res,
                                          int K, int N, int bx, int by,
                                          uint32_t* As, uint32_t* Bs) {
    int tid  = threadIdx.x;
    int lane = tid & 31, warp = tid >> 5;
    int warpM = (warp & 1) * 64;
    int warpN = (warp >> 1) * 32;
    int rowBase = by * BMT, colBase = bx * BNT;
    const float* Ab = A + (size_t)rowBase * K;
    const float* Wb = W + (size_t)colBase * K;

    int r0 = tid >> 2,         kq = (tid & 3) * 4;
    int r1 = (tid + 256) >> 2;

    float4 a4[2], b4[2];

    float acc[4][4][4];
#pragma unroll
    for (int i = 0; i < 4; i++)
#pragma unroll
        for (int j = 0; j < 4; j++)
#pragma unroll
            for (int q = 0; q < 4; q++) acc[i][j][q] = 0.f;

    a4[0] = *(const float4*)(Ab + (size_t)r0 * K + kq);
    a4[1] = *(const float4*)(Ab + (size_t)r1 * K + kq);
    b4[0] = *(const float4*)(Wb + (size_t)r0 * K + kq);
    b4[1] = *(const float4*)(Wb + (size_t)r1 * K + kq);
    {
        uint32_t* a = As; uint32_t* bsm = Bs;
        a[r0*SST+kq+0]=f2tf(a4[0].x); a[r0*SST+kq+1]=f2tf(a4[0].y);
        a[r0*SST+kq+2]=f2tf(a4[0].z); a[r0*SST+kq+3]=f2tf(a4[0].w);
        a[r1*SST+kq+0]=f2tf(a4[1].x); a[r1*SST+kq+1]=f2tf(a4[1].y);
        a[r1*SST+kq+2]=f2tf(a4[1].z); a[r1*SST+kq+3]=f2tf(a4[1].w);
        bsm[r0*SST+kq+0]=f2tf(b4[0].x); bsm[r0*SST+kq+1]=f2tf(b4[0].y);
        bsm[r0*SST+kq+2]=f2tf(b4[0].z); bsm[r0*SST+kq+3]=f2tf(b4[0].w);
        bsm[r1*SST+kq+0]=f2tf(b4[1].x); bsm[r1*SST+kq+1]=f2tf(b4[1].y);
        bsm[r1*SST+kq+2]=f2tf(b4[1].z); bsm[r1*SST+kq+3]=f2tf(b4[1].w);
    }
    __syncthreads();

    int nc = K / BKT;
    for (int c = 0; c < nc; ++c) {
        int buf = c & 1;
        if (c + 1 < nc) {
            int k0 = (c + 1) * BKT;
            a4[0] = *(const float4*)(Ab + (size_t)r0 * K + k0 + kq);
            a4[1] = *(const float4*)(Ab + (size_t)r1 * K + k0 + kq);
            b4[0] = *(const float4*)(Wb + (size_t)r0 * K + k0 + kq);
            b4[1] = *(const float4*)(Wb + (size_t)r1 * K + k0 + kq);
        }
        const uint32_t* as  = As + buf * (BMT * SST);
        const uint32_t* bsm = Bs + buf * (BNT * SST);
#pragma unroll
        for (int ks = 0; ks < 2; ++ks) {
            int kb = ks * 8 + (lane & 3);
            uint32_t af[4][4], bf[4][2];
#pragma unroll
            for (int mt = 0; mt < 4; ++mt) {
                int rr = warpM + mt * 16 + (lane >> 2);
                af[mt][0] = as[rr * SST + kb];
                af[mt][1] = as[(rr + 8) * SST + kb];
                af[mt][2] = as[rr * SST + kb + 4];
                af[mt][3] = as[(rr + 8) * SST + kb + 4];
            }
#pragma unroll
            for (int nt = 0; nt < 4; ++nt) {
                int cc = warpN + nt * 8 + (lane >> 2);
                bf[nt][0] = bsm[cc * SST + kb];
                bf[nt][1] = bsm[cc * SST + kb + 4];
            }
#pragma unroll
            for (int mt = 0; mt < 4; ++mt)
#pragma unroll
                for (int nt = 0; nt < 4; ++nt)
                    mma_tf32(acc[mt][nt], af[mt], bf[nt]);
        }
        if (c + 1 < nc) {
            uint32_t* a  = As + (buf ^ 1) * (BMT * SST);
            uint32_t* bb = Bs + (buf ^ 1) * (BNT * SST);
            a[r0*SST+kq+0]=f2tf(a4[0].x); a[r0*SST+kq+1]=f2tf(a4[0].y);
            a[r0*SST+kq+2]=f2tf(a4[0].z); a[r0*SST+kq+3]=f2tf(a4[0].w);
            a[r1*SST+kq+0]=f2tf(a4[1].x); a[r1*SST+kq+1]=f2tf(a4[1].y);
            a[r1*SST+kq+2]=f2tf(a4[1].z); a[r1*SST+kq+3]=f2tf(a4[1].w);
            bb[r0*SST+kq+0]=f2tf(b4[0].x); bb[r0*SST+kq+1]=f2tf(b4[0].y);
            bb[r0*SST+kq+2]=f2tf(b4[0].z); bb[r0*SST+kq+3]=f2tf(b4[0].w);
            bb[r1*SST+kq+0]=f2tf(b4[1].x); bb[r1*SST+kq+1]=f2tf(b4[1].y);
            bb[r1*SST+kq+2]=f2tf(b4[1].z); bb[r1*SST+kq+3]=f2tf(b4[1].w);
            __syncthreads();
        }
    }

#pragma unroll
    for (int nt = 0; nt < 4; ++nt) {
        int col = colBase + warpN + nt * 8 + 2 * (lane & 3);
        float bv0 = 0.f, bv1 = 0.f;
        if (bias) { bv0 = bias[col]; bv1 = bias[col + 1]; }
#pragma unroll
        for (int mt = 0; mt < 4; ++mt) {
#pragma unroll
            for (int half = 0; half < 2; ++half) {
                int row = rowBase + warpM + mt * 16 + (lane >> 2) + half * 8;
                float v0 = acc[mt][nt][half * 2 + 0] + bv0;
                float v1 = acc[mt][nt][half * 2 + 1] + bv1;
                if (EPI == 1) {
                    v0 = 0.5f * v0 * (1.f + erff(v0 * 0.70710678118654752f));
                    v1 = 0.5f * v1 * (1.f + erff(v1 * 0.70710678118654752f));
                } else if (EPI == 2) {
                    const float* rr = res + (size_t)row * N + col;
                    v0 += rr[0]; v1 += rr[1];
                }
                float2 o = make_float2(v0, v1);
                *(float2*)(C + (size_t)row * N + col) = o;
            }
        }
    }
}

template <int EPI>
__global__ void __launch_bounds__(256)
gemm_tc(const float* __restrict__ A, const float* __restrict__ W,
        const float* __restrict__ bias, float* __restrict__ C,
        const float* __restrict__ res, int K, int N) {
    __shared__ uint32_t As[2 * BMT * SST];
    __shared__ uint32_t Bs[2 * BNT * SST];
    gemm_body<EPI>(A, W, bias, C, res, K, N, blockIdx.x, blockIdx.y, As, Bs);
}

__global__ void __launch_bounds__(256)
qkv_tc(const float* __restrict__ A,
       const float* __restrict__ Wq, const float* __restrict__ bq, float* __restrict__ Cq,
       const float* __restrict__ Wk, const float* __restrict__ bk, float* __restrict__ Ck,
       const float* __restrict__ Wv, const float* __restrict__ bv, float* __restrict__ Cv) {
    __shared__ uint32_t As[2 * BMT * SST];
    __shared__ uint32_t Bs[2 * BNT * SST];
    const float* W; const float* bias; float* C;
    if (blockIdx.z == 0)      { W = Wq; bias = bq; C = Cq; }
    else if (blockIdx.z == 1) { W = Wk; bias = bk; C = Ck; }
    else                      { W = Wv; bias = bv; C = Cv; }
    gemm_body<0>(A, W, bias, C, nullptr, DD, DD, blockIdx.x, blockIdx.y, As, Bs);
}

// ---------------- flash attention (TF32 mma, online softmax) ----------------
// grid: (MP/BQ, B*H), 128 threads (4 warps, 16 q-rows each)
__global__ void __launch_bounds__(128)
flash_attn(const float* __restrict__ Qg, const float* __restrict__ Kg,
           const float* __restrict__ Vg, float* __restrict__ Y) {
    int qt = gridDim.x - 1 - blockIdx.x;   // heavy tiles first
    int bh = blockIdx.y;
    int b = bh >> 4, h = bh & 15;
    extern __shared__ uint32_t sm[];
    uint32_t* Qs = sm;
    uint32_t* Ks = sm + BQ * AST;
    uint32_t* Vs = sm + 2 * BQ * AST;
    uint32_t* Ps = sm + 3 * BQ * AST;
    int tid = threadIdx.x, lane = tid & 31, warp = tid >> 5;
    size_t base = (size_t)b * MP * DD + (size_t)h * DHH;

    // load Q tile (tf32)
    {
        int r = tid >> 1, c0 = (tid & 1) * 32;
        const float* src = Qg + base + (size_t)(qt * BQ + r) * DD + c0;
        uint32_t* dst = Qs + r * AST + c0;
#pragma unroll
        for (int i = 0; i < 8; i++) {
            float4 v = ((const float4*)src)[i];
            *(uint4*)(dst + 4 * i) = make_uint4(f2tf(v.x), f2tf(v.y), f2tf(v.z), f2tf(v.w));
        }
    }

    const float SC = 0.125f * 1.4426950408889634f;  // 1/sqrt(64) * log2(e)
    float m0 = -1e30f, m1 = -1e30f, l0 = 0.f, l1 = 0.f;
    float o[8][4];
#pragma unroll
    for (int nt = 0; nt < 8; nt++) { o[nt][0] = o[nt][1] = o[nt][2] = o[nt][3] = 0.f; }
    int rloc = warp * 16 + (lane >> 2);

    for (int kt = 0; kt <= qt; kt++) {
        __syncthreads();   // prev iter done with Ks/Vs (and Q store visible on iter 0)
        {
            int r = tid >> 1, c0 = (tid & 1) * 32;
            const float* ks = Kg + base + (size_t)(kt * BK + r) * DD + c0;
            const float* vs = Vg + base + (size_t)(kt * BK + r) * DD + c0;
            uint32_t* kd = Ks + r * AST + c0;
            uint32_t* vd = Vs + r * AST + c0;
#pragma unroll
            for (int i = 0; i < 8; i++) {
                float4 kv = ((const float4*)ks)[i];
                float4 vv = ((const float4*)vs)[i];
                *(uint4*)(kd + 4 * i) = make_uint4(f2tf(kv.x), f2tf(kv.y), f2tf(kv.z), f2tf(kv.w));
                *(uint4*)(vd + 4 * i) = make_uint4(f2tf(vv.x), f2tf(vv.y), f2tf(vv.z), f2tf(vv.w));
            }
        }
        __syncthreads();

        // S = Q K^T  (warp's 16 rows x 64 cols)
        float s[8][4];
#pragma unroll
        for (int nt = 0; nt < 8; nt++) { s[nt][0] = s[nt][1] = s[nt][2] = s[nt][3] = 0.f; }
#pragma unroll
        for (int kc = 0; kc < 8; kc++) {
            int kb = kc * 8 + (lane & 3);
            uint32_t af[4];
            af[0] = Qs[rloc * AST + kb];
            af[1] = Qs[(rloc + 8) * AST + kb];
            af[2] = Qs[rloc * AST + kb + 4];
            af[3] = Qs[(rloc + 8) * AST + kb + 4];
#pragma unroll
            for (int nt = 0; nt < 8; nt++) {
                int cc = nt * 8 + (lane >> 2);
                uint32_t bf[2] = { Ks[cc * AST + kb], Ks[cc * AST + kb + 4] };
                mma_tf32(s[nt], af, bf);
            }
        }

        if (kt == qt) {  // causal mask on diagonal tile
#pragma unroll
            for (int nt = 0; nt < 8; nt++) {
                int c0 = nt * 8 + 2 * (lane & 3);
                if (c0     > rloc)     s[nt][0] = -1e30f;
                if (c0 + 1 > rloc)     s[nt][1] = -1e30f;
                if (c0     > rloc + 8) s[nt][2] = -1e30f;
                if (c0 + 1 > rloc + 8) s[nt][3] = -1e30f;
            }
        }

        // row max (quad shuffle: lanes sharing a row are xor-1,2 neighbors)
        float t0 = -1e30f, t1 = -1e30f;
#pragma unroll
        for (int nt = 0; nt < 8; nt++) {
            t0 = fmaxf(t0, fmaxf(s[nt][0], s[nt][1]));
            t1 = fmaxf(t1, fmaxf(s[nt][2], s[nt][3]));
        }
        t0 = fmaxf(t0, __shfl_xor_sync(0xffffffffu, t0, 1));
        t0 = fmaxf(t0, __shfl_xor_sync(0xffffffffu, t0, 2));
        t1 = fmaxf(t1, __shfl_xor_sync(0xffffffffu, t1, 1));
        t1 = fmaxf(t1, __shfl_xor_sync(0xffffffffu, t1, 2));
        float mn0 = fmaxf(m0, t0), mn1 = fmaxf(m1, t1);
        float sc0 = exp2f((m0 - mn0) * SC), sc1 = exp2f((m1 - mn1) * SC);
        m0 = mn0; m1 = mn1;

        // P = exp2((s-m)*SC); store to per-warp-private smem rows
        float rs0 = 0.f, rs1 = 0.f;
#pragma unroll
        for (int nt = 0; nt < 8; nt++) {
            float p0 = exp2f((s[nt][0] - m0) * SC);
            float p1 = exp2f((s[nt][1] - m0) * SC);
            float p2 = exp2f((s[nt][2] - m1) * SC);
            float p3 = exp2f((s[nt][3] - m1) * SC);
            rs0 += p0 + p1; rs1 += p2 + p3;
            int c0 = nt * 8 + 2 * (lane & 3);
            Ps[rloc * AST + c0]           = f2tf(p0);
            Ps[rloc * AST + c0 + 1]       = f2tf(p1);
            Ps[(rloc + 8) * AST + c0]     = f2tf(p2);
            Ps[(rloc + 8) * AST + c0 + 1] = f2tf(p3);
        }
        rs0 += __shfl_xor_sync(0xffffffffu, rs0, 1);
        rs0 += __shfl_xor_sync(0xffffffffu, rs0, 2);
        rs1 += __shfl_xor_sync(0xffffffffu, rs1, 1);
        rs1 += __shfl_xor_sync(0xffffffffu, rs1, 2);
        l0 = l0 * sc0 + rs0; l1 = l1 * sc1 + rs1;

#pragma unroll
        for (int nt = 0; nt < 8; nt++) {
            o[nt][0] *= sc0; o[nt][1] *= sc0; o[nt][2] *= sc1; o[nt][3] *= sc1;
        }
        __syncwarp();

        // O += P V
#pragma unroll
        for (int kc = 0; kc < 8; kc++) {
            int kb = kc * 8 + (lane & 3);
            uint32_t af[4];
            af[0] = Ps[rloc * AST + kb];
            af[1] = Ps[(rloc + 8) * AST + kb];
            af[2] = Ps[rloc * AST + kb + 4];
            af[3] = Ps[(rloc + 8) * AST + kb + 4];
#pragma unroll
            for (int nt = 0; nt < 8; nt++) {
                int cc = nt * 8 + (lane >> 2);
                uint32_t bf[2] = { Vs[kb * AST + cc], Vs[(kb + 4) * AST + cc] };
                mma_tf32(o[nt], af, bf);
            }
        }
    }

    float inv0 = 1.f / l0, inv1 = 1.f / l1;
    int grow = qt * BQ + rloc;
#pragma unroll
    for (int nt = 0; nt < 8; nt++) {
        int c0 = nt * 8 + 2 * (lane & 3);
        *(float2*)(Y + base + (size_t)grow * DD + c0)       = make_float2(o[nt][0] * inv0, o[nt][1] * inv0);
        *(float2*)(Y + base + (size_t)(grow + 8) * DD + c0) = make_float2(o[nt][2] * inv1, o[nt][3] * inv1);
    }
}

// ---------------- launcher ----------------
extern "C" void kernel_launch(void* const* d_in, const int* in_sizes, int n_in,
                              void* d_out, int out_size) {
    const float* states  = (const float*)d_in[0];
    const int*   actions = (const int*)  d_in[1];
    const float* rtg     = (const float*)d_in[2];
    const int*   tsteps  = (const int*)  d_in[3];
    const float* pos_emb = (const float*)d_in[4];
    const float* gpe     = (const float*)d_in[5];
    const float* Ws      = (const float*)d_in[6];
    const float* bs      = (const float*)d_in[7];
    const float* Wr      = (const float*)d_in[8];
    const float* br      = (const float*)d_in[9];
    const float* aemb    = (const float*)d_in[10];
    const float* ln1_g   = (const float*)d_in[11];
    const float* ln1_b   = (const float*)d_in[12];
    const float* Wq      = (const float*)d_in[13];
    const float* bq      = (const float*)d_in[14];
    const float* Wk      = (const float*)d_in[15];
    const float* bk      = (const float*)d_in[16];
    const float* Wv      = (const float*)d_in[17];
    const float* bv      = (const float*)d_in[18];
    const float* Wo      = (const float*)d_in[19];
    const float* bo      = (const float*)d_in[20];
    const float* ln2_g   = (const float*)d_in[21];
    const float* ln2_b   = (const float*)d_in[22];
    const float* W1      = (const float*)d_in[23];
    const float* b1      = (const float*)d_in[24];
    const float* W2      = (const float*)d_in[25];
    const float* b2      = (const float*)d_in[26];
    const float* lnf_g   = (const float*)d_in[27];
    const float* lnf_b   = (const float*)d_in[28];
    const float* head_W  = (const float*)d_in[29];

    float *x, *hb, *qb, *kb, *vb, *yb, *ffb;
    cudaGetSymbolAddress((void**)&x,  g_x);
    cudaGetSymbolAddress((void**)&hb, g_h);
    cudaGetSymbolAddress((void**)&qb, g_q);
    cudaGetSymbolAddress((void**)&kb, g_k);
    cudaGetSymbolAddress((void**)&vb, g_v);
    cudaGetSymbolAddress((void**)&yb, g_y);
    cudaGetSymbolAddress((void**)&ffb, g_ff);

    cudaFuncSetAttribute(flash_attn, cudaFuncAttributeMaxDynamicSharedMemorySize, ATTN_SMEM);

    embed_kernel<<<dim3(MP, BB), 256>>>(states, actions, rtg, tsteps,
                                        pos_emb, gpe, Ws, bs, Wr, br, aemb);

    for (int l = 0; l < LL; ++l) {
        size_t wOff = (size_t)l * DD * DD;
        size_t bOff = (size_t)l * DD;
        ln_kernel<<<ROWS, 256>>>(x, ln1_g + bOff, ln1_b + bOff, hb);
        qkv_tc<<<dim3(DD / BNT, ROWS / BMT, 3), 256>>>(hb,
            Wq + wOff, bq + bOff, qb,
            Wk + wOff, bk + bOff, kb,
            Wv + wOff, bv + bOff, vb);
        flash_attn<<<dim3(MP / BQ, BB * HH), 128, ATTN_SMEM>>>(qb, kb, vb, yb);
        gemm_tc<2><<<dim3(DD / BNT, ROWS / BMT), 256>>>(yb, Wo + wOff, bo + bOff, x, x, DD, DD);
        ln_kernel<<<ROWS, 256>>>(x, ln2_g + bOff, ln2_b + bOff, hb);
        gemm_tc<1><<<dim3(FFD / BNT, ROWS / BMT), 256>>>(hb, W1 + (size_t)l * FFD * DD,
                                                         b1 + (size_t)l * FFD, ffb, nullptr, DD, FFD);
        gemm_tc<2><<<dim3(DD / BNT, ROWS / BMT), 256>>>(ffb, W2 + (size_t)l * DD * FFD,
                                                        b2 + bOff, x, x, FFD, DD);
    }

    gather_ln_kernel<<<BB * TSZ, 256>>>(x, lnf_g, lnf_b, hb);
    gemm_tc<0><<<dim3(VV / BNT, (BB * TSZ) / BMT), 256>>>(hb, head_W, nullptr,
                                                          (float*)d_out, nullptr, DD, VV);
}

// round 9
// speedup vs baseline: 3.6864x; 1.1292x over previous
#include <cuda_runtime.h>
#include <cuda_fp16.h>
#include <math.h>
#include <stdint.h>

#define BB   4
#define TSZ  256
#define DD   1024
#define HH   16
#define DHH  64
#define LL   4
#define VV   32000
#define FFD  4096
#define MM   767
#define MP   768
#define ROWS (BB*MP)   /* 3072 */

// fp16 GEMM tile params: 128x128 tile, K-chunk = 32
#define BMT 128
#define BNT 128
#define BKH 32     /* K elems per chunk */
#define SSTH 20    /* smem row stride in half2 units (16 data + 4 pad) */

// flash attention tile params
#define BQ  64
#define BK  64
#define AST 68
#define ATTN_SMEM (4 * BQ * AST * 4)

// ---------------- scratch (device globals) ----------------
__device__ float g_x [ROWS*DD];
__device__ float g_h [ROWS*DD];
__device__ float g_q [ROWS*DD];
__device__ float g_k [ROWS*DD];
__device__ float g_v [ROWS*DD];
__device__ float g_y [ROWS*DD];
__device__ float g_ff[ROWS*FFD];

// ---------------- helpers ----------------
__device__ __forceinline__ float blk_sum(float v, float* sh) {
    int lane = threadIdx.x & 31, w = threadIdx.x >> 5;
#pragma unroll
    for (int o = 16; o; o >>= 1) v += __shfl_down_sync(0xffffffffu, v, o);
    if (lane == 0) sh[w] = v;
    __syncthreads();
    if (w == 0) {
        float t = (lane < (int)(blockDim.x >> 5)) ? sh[lane] : 0.f;
#pragma unroll
        for (int o = 16; o; o >>= 1) t += __shfl_down_sync(0xffffffffu, t, o);
        if (lane == 0) sh[0] = t;
    }
    __syncthreads();
    float r = sh[0];
    __syncthreads();
    return r;
}

__device__ __forceinline__ uint32_t f2tf(float f) {
    uint32_t u;
    asm("cvt.rna.tf32.f32 %0, %1;" : "=r"(u) : "f"(f));
    return u;
}

__device__ __forceinline__ uint32_t f2h2(float x, float y) {
    __half2 h = __floats2half2_rn(x, y);
    return *(uint32_t*)&h;
}

__device__ __forceinline__ void mma_tf32(float* c, const uint32_t* a, const uint32_t* b) {
    asm volatile(
        "mma.sync.aligned.m16n8k8.row.col.f32.tf32.tf32.f32 "
        "{%0,%1,%2,%3},{%4,%5,%6,%7},{%8,%9},{%0,%1,%2,%3};"
        : "+f"(c[0]), "+f"(c[1]), "+f"(c[2]), "+f"(c[3])
        : "r"(a[0]), "r"(a[1]), "r"(a[2]), "r"(a[3]), "r"(b[0]), "r"(b[1]));
}

__device__ __forceinline__ void mma_f16(float* c, const uint32_t* a, const uint32_t* b) {
    asm volatile(
        "mma.sync.aligned.m16n8k16.row.col.f32.f16.f16.f32 "
        "{%0,%1,%2,%3},{%4,%5,%6,%7},{%8,%9},{%0,%1,%2,%3};"
        : "+f"(c[0]), "+f"(c[1]), "+f"(c[2]), "+f"(c[3])
        : "r"(a[0]), "r"(a[1]), "r"(a[2]), "r"(a[3]), "r"(b[0]), "r"(b[1]));
}

// ---------------- embedding ----------------
__global__ void embed_kernel(const float* __restrict__ states,
                             const int*   __restrict__ actions,
                             const float* __restrict__ rtg,
                             const int*   __restrict__ timesteps,
                             const float* __restrict__ pos_emb,
                             const float* __restrict__ gpe,
                             const float* __restrict__ Ws, const float* __restrict__ bs,
                             const float* __restrict__ Wr, const float* __restrict__ br,
                             const float* __restrict__ aemb) {
    int m = blockIdx.x;
    int b = blockIdx.y;
    float* out = g_x + ((size_t)(b * MP + m)) * DD;
    if (m >= MM) {
        for (int d = threadIdx.x; d < DD; d += blockDim.x) out[d] = 0.f;
        return;
    }
    int ts = timesteps[b];
    int r = m % 3, t = m / 3;
    float sv = 0.f; int ai = 0;
    if (r == 0) sv = rtg[b * TSZ + t];
    else if (r == 1) sv = states[b * TSZ + t];
    else ai = actions[b * TSZ + t + 1];
    for (int d = threadIdx.x; d < DD; d += blockDim.x) {
        float tok;
        if (r == 0)      tok = tanhf(sv * Wr[d] + br[d]);
        else if (r == 1) tok = tanhf(sv * Ws[d] + bs[d]);
        else             tok = tanhf(aemb[(size_t)ai * DD + d]);
        out[d] = tok + gpe[(size_t)ts * DD + d] + pos_emb[(size_t)m * DD + d];
    }
}

// ---------------- layernorm ----------------
__device__ __forceinline__ void ln_row(const float* __restrict__ xin,
                                       const float* __restrict__ g,
                                       const float* __restrict__ b,
                                       float* __restrict__ yout,
                                       float* red) {
    int t = threadIdx.x;
    float4 v = ((const float4*)xin)[t];
    float s  = v.x + v.y + v.z + v.w;
    float ss = v.x * v.x + v.y * v.y + v.z * v.z + v.w * v.w;
    float mean = blk_sum(s, red) * (1.f / DD);
    float var  = blk_sum(ss, red) * (1.f / DD) - mean * mean;
    float rs = rsqrtf(var + 1e-5f);
    float4 gg = ((const float4*)g)[t];
    float4 bb = ((const float4*)b)[t];
    float4 o;
    o.x = (v.x - mean) * rs * gg.x + bb.x;
    o.y = (v.y - mean) * rs * gg.y + bb.y;
    o.z = (v.z - mean) * rs * gg.z + bb.z;
    o.w = (v.w - mean) * rs * gg.w + bb.w;
    ((float4*)yout)[t] = o;
}

__global__ void ln_kernel(const float* __restrict__ in,
                          const float* __restrict__ g,
                          const float* __restrict__ b,
                          float* __restrict__ out) {
    __shared__ float red[32];
    size_t row = blockIdx.x;
    ln_row(in + row * DD, g, b, out + row * DD, red);
}

__global__ void gather_ln_kernel(const float* __restrict__ in,
                                 const float* __restrict__ g,
                                 const float* __restrict__ b,
                                 float* __restrict__ out) {
    __shared__ float red[32];
    int i = blockIdx.x;
    int bb = i >> 8, t = i & 255;
    size_t row = (size_t)bb * MP + 1 + 3 * t;
    ln_row(in + row * DD, g, b, out + (size_t)i * DD, red);
}

// ---------------- FP16 tensor-core GEMM ----------------
// C[rows,N] = A[rows,K] @ W[N,K]^T (+bias, epilogue). EPI: 0=none, 1=gelu, 2=+res
// Smem: half2 rows, 16 data + 4 pad per 32-K chunk row.
template <int EPI>
__device__ __forceinline__ void gemm_body(const float* __restrict__ A,
                                          const float* __restrict__ W,
                                          const float* __restrict__ bias,
                                          float* __restrict__ C,
                                          const float* __restrict__ res,
                                          int K, int N, int bx, int by,
                                          uint32_t* As, uint32_t* Bs) {
    int tid  = threadIdx.x;
    int lane = tid & 31, warp = tid >> 5;
    int warpM = (warp & 1) * 64;
    int warpN = (warp >> 1) * 32;
    int rowBase = by * BMT, colBase = bx * BNT;
    const float* Ab = A + (size_t)rowBase * K;
    const float* Wb = W + (size_t)colBase * K;

    // global->smem: thread handles row r0 = tid>>1, 16 floats at offset (tid&1)*16
    int r0 = tid >> 1, sg = (tid & 1) * 16;
    int hoff = r0 * SSTH + (tid & 1) * 8;   // half2 index

    float4 a4[4], b4[4];

    float acc[4][4][4];
#pragma unroll
    for (int i = 0; i < 4; i++)
#pragma unroll
        for (int j = 0; j < 4; j++)
#pragma unroll
            for (int q = 0; q < 4; q++) acc[i][j][q] = 0.f;

#pragma unroll
    for (int i = 0; i < 4; i++) {
        a4[i] = *(const float4*)(Ab + (size_t)r0 * K + sg + 4 * i);
        b4[i] = *(const float4*)(Wb + (size_t)r0 * K + sg + 4 * i);
    }
    {
        uint4 ha0 = make_uint4(f2h2(a4[0].x, a4[0].y), f2h2(a4[0].z, a4[0].w),
                               f2h2(a4[1].x, a4[1].y), f2h2(a4[1].z, a4[1].w));
        uint4 ha1 = make_uint4(f2h2(a4[2].x, a4[2].y), f2h2(a4[2].z, a4[2].w),
                               f2h2(a4[3].x, a4[3].y), f2h2(a4[3].z, a4[3].w));
        uint4 hb0 = make_uint4(f2h2(b4[0].x, b4[0].y), f2h2(b4[0].z, b4[0].w),
                               f2h2(b4[1].x, b4[1].y), f2h2(b4[1].z, b4[1].w));
        uint4 hb1 = make_uint4(f2h2(b4[2].x, b4[2].y), f2h2(b4[2].z, b4[2].w),
                               f2h2(b4[3].x, b4[3].y), f2h2(b4[3].z, b4[3].w));
        *(uint4*)(As + hoff)     = ha0;
        *(uint4*)(As + hoff + 4) = ha1;
        *(uint4*)(Bs + hoff)     = hb0;
        *(uint4*)(Bs + hoff + 4) = hb1;
    }
    __syncthreads();

    int nc = K / BKH;
    for (int c = 0; c < nc; ++c) {
        int buf = c & 1;
        if (c + 1 < nc) {
            int k0 = (c + 1) * BKH;
#pragma unroll
            for (int i = 0; i < 4; i++) {
                a4[i] = *(const float4*)(Ab + (size_t)r0 * K + k0 + sg + 4 * i);
                b4[i] = *(const float4*)(Wb + (size_t)r0 * K + k0 + sg + 4 * i);
            }
        }
        const uint32_t* as  = As + buf * (BMT * SSTH);
        const uint32_t* bsm = Bs + buf * (BNT * SSTH);
#pragma unroll
        for (int ks = 0; ks < 2; ++ks) {
            int kb = ks * 8 + (lane & 3);
            uint32_t af[4][4], bf[4][2];
#pragma unroll
            for (int mt = 0; mt < 4; ++mt) {
                int rr = warpM + mt * 16 + (lane >> 2);
                af[mt][0] = as[rr * SSTH + kb];
                af[mt][1] = as[(rr + 8) * SSTH + kb];
                af[mt][2] = as[rr * SSTH + kb + 4];
                af[mt][3] = as[(rr + 8) * SSTH + kb + 4];
            }
#pragma unroll
            for (int nt = 0; nt < 4; ++nt) {
                int cc = warpN + nt * 8 + (lane >> 2);
                bf[nt][0] = bsm[cc * SSTH + kb];
                bf[nt][1] = bsm[cc * SSTH + kb + 4];
            }
#pragma unroll
            for (int mt = 0; mt < 4; ++mt)
#pragma unroll
                for (int nt = 0; nt < 4; ++nt)
                    mma_f16(acc[mt][nt], af[mt], bf[nt]);
        }
        if (c + 1 < nc) {
            uint32_t* a  = As + (buf ^ 1) * (BMT * SSTH);
            uint32_t* bb = Bs + (buf ^ 1) * (BNT * SSTH);
            uint4 ha0 = make_uint4(f2h2(a4[0].x, a4[0].y), f2h2(a4[0].z, a4[0].w),
                                   f2h2(a4[1].x, a4[1].y), f2h2(a4[1].z, a4[1].w));
            uint4 ha1 = make_uint4(f2h2(a4[2].x, a4[2].y), f2h2(a4[2].z, a4[2].w),
                                   f2h2(a4[3].x, a4[3].y), f2h2(a4[3].z, a4[3].w));
            uint4 hb0 = make_uint4(f2h2(b4[0].x, b4[0].y), f2h2(b4[0].z, b4[0].w),
                                   f2h2(b4[1].x, b4[1].y), f2h2(b4[1].z, b4[1].w));
            uint4 hb1 = make_uint4(f2h2(b4[2].x, b4[2].y), f2h2(b4[2].z, b4[2].w),
                                   f2h2(b4[3].x, b4[3].y), f2h2(b4[3].z, b4[3].w));
            *(uint4*)(a + hoff)      = ha0;
            *(uint4*)(a + hoff + 4)  = ha1;
            *(uint4*)(bb + hoff)     = hb0;
            *(uint4*)(bb + hoff + 4) = hb1;
            __syncthreads();
        }
    }

#pragma unroll
    for (int nt = 0; nt < 4; ++nt) {
        int col = colBase + warpN + nt * 8 + 2 * (lane & 3);
        float bv0 = 0.f, bv1 = 0.f;
        if (bias) { bv0 = bias[col]; bv1 = bias[col + 1]; }
#pragma unroll
        for (int mt = 0; mt < 4; ++mt) {
#pragma unroll
            for (int half = 0; half < 2; ++half) {
                int row = rowBase + warpM + mt * 16 + (lane >> 2) + half * 8;
                float v0 = acc[mt][nt][half * 2 + 0] + bv0;
                float v1 = acc[mt][nt][half * 2 + 1] + bv1;
                if (EPI == 1) {
                    v0 = 0.5f * v0 * (1.f + erff(v0 * 0.70710678118654752f));
                    v1 = 0.5f * v1 * (1.f + erff(v1 * 0.70710678118654752f));
                } else if (EPI == 2) {
                    const float* rr = res + (size_t)row * N + col;
                    v0 += rr[0]; v1 += rr[1];
                }
                float2 o = make_float2(v0, v1);
                *(float2*)(C + (size_t)row * N + col) = o;
            }
        }
    }
}

template <int EPI>
__global__ void __launch_bounds__(256)
gemm_tc(const float* __restrict__ A, const float* __restrict__ W,
        const float* __restrict__ bias, float* __restrict__ C,
        const float* __restrict__ res, int K, int N) {
    __shared__ uint32_t As[2 * BMT * SSTH];
    __shared__ uint32_t Bs[2 * BNT * SSTH];
    gemm_body<EPI>(A, W, bias, C, res, K, N, blockIdx.x, blockIdx.y, As, Bs);
}

__global__ void __launch_bounds__(256)
qkv_tc(const float* __restrict__ A,
       const float* __restrict__ Wq, const float* __restrict__ bq, float* __restrict__ Cq,
       const float* __restrict__ Wk, const float* __restrict__ bk, float* __restrict__ Ck,
       const float* __restrict__ Wv, const float* __restrict__ bv, float* __restrict__ Cv) {
    __shared__ uint32_t As[2 * BMT * SSTH];
    __shared__ uint32_t Bs[2 * BNT * SSTH];
    const float* W; const float* bias; float* C;
    if (blockIdx.z == 0)      { W = Wq; bias = bq; C = Cq; }
    else if (blockIdx.z == 1) { W = Wk; bias = bk; C = Ck; }
    else                      { W = Wv; bias = bv; C = Cv; }
    gemm_body<0>(A, W, bias, C, nullptr, DD, DD, blockIdx.x, blockIdx.y, As, Bs);
}

// ---------------- flash attention (TF32 mma, online softmax) ----------------
// grid: (MP/BQ, B*H), 128 threads (4 warps, 16 q-rows each)
__global__ void __launch_bounds__(128)
flash_attn(const float* __restrict__ Qg, const float* __restrict__ Kg,
           const float* __restrict__ Vg, float* __restrict__ Y) {
    int qt = gridDim.x - 1 - blockIdx.x;   // heavy tiles first
    int bh = blockIdx.y;
    int b = bh >> 4, h = bh & 15;
    extern __shared__ uint32_t sm[];
    uint32_t* Qs = sm;
    uint32_t* Ks = sm + BQ * AST;
    uint32_t* Vs = sm + 2 * BQ * AST;
    uint32_t* Ps = sm + 3 * BQ * AST;
    int tid = threadIdx.x, lane = tid & 31, warp = tid >> 5;
    size_t base = (size_t)b * MP * DD + (size_t)h * DHH;

    {
        int r = tid >> 1, c0 = (tid & 1) * 32;
        const float* src = Qg + base + (size_t)(qt * BQ + r) * DD + c0;
        uint32_t* dst = Qs + r * AST + c0;
#pragma unroll
        for (int i = 0; i < 8; i++) {
            float4 v = ((const float4*)src)[i];
            *(uint4*)(dst + 4 * i) = make_uint4(f2tf(v.x), f2tf(v.y), f2tf(v.z), f2tf(v.w));
        }
    }

    const float SC = 0.125f * 1.4426950408889634f;  // 1/sqrt(64) * log2(e)
    float m0 = -1e30f, m1 = -1e30f, l0 = 0.f, l1 = 0.f;
    float o[8][4];
#pragma unroll
    for (int nt = 0; nt < 8; nt++) { o[nt][0] = o[nt][1] = o[nt][2] = o[nt][3] = 0.f; }
    int rloc = warp * 16 + (lane >> 2);

    for (int kt = 0; kt <= qt; kt++) {
        __syncthreads();
        {
            int r = tid >> 1, c0 = (tid & 1) * 32;
            const float* ks = Kg + base + (size_t)(kt * BK + r) * DD + c0;
            const float* vs = Vg + base + (size_t)(kt * BK + r) * DD + c0;
            uint32_t* kd = Ks + r * AST + c0;
            uint32_t* vd = Vs + r * AST + c0;
#pragma unroll
            for (int i = 0; i < 8; i++) {
                float4 kv = ((const float4*)ks)[i];
                float4 vv = ((const float4*)vs)[i];
                *(uint4*)(kd + 4 * i) = make_uint4(f2tf(kv.x), f2tf(kv.y), f2tf(kv.z), f2tf(kv.w));
                *(uint4*)(vd + 4 * i) = make_uint4(f2tf(vv.x), f2tf(vv.y), f2tf(vv.z), f2tf(vv.w));
            }
        }
        __syncthreads();

        float s[8][4];
#pragma unroll
        for (int nt = 0; nt < 8; nt++) { s[nt][0] = s[nt][1] = s[nt][2] = s[nt][3] = 0.f; }
#pragma unroll
        for (int kc = 0; kc < 8; kc++) {
            int kb = kc * 8 + (lane & 3);
            uint32_t af[4];
            af[0] = Qs[rloc * AST + kb];
            af[1] = Qs[(rloc + 8) * AST + kb];
            af[2] = Qs[rloc * AST + kb + 4];
            af[3] = Qs[(rloc + 8) * AST + kb + 4];
#pragma unroll
            for (int nt = 0; nt < 8; nt++) {
                int cc = nt * 8 + (lane >> 2);
                uint32_t bf[2] = { Ks[cc * AST + kb], Ks[cc * AST + kb + 4] };
                mma_tf32(s[nt], af, bf);
            }
        }

        if (kt == qt) {
#pragma unroll
            for (int nt = 0; nt < 8; nt++) {
                int c0 = nt * 8 + 2 * (lane & 3);
                if (c0     > rloc)     s[nt][0] = -1e30f;
                if (c0 + 1 > rloc)     s[nt][1] = -1e30f;
                if (c0     > rloc + 8) s[nt][2] = -1e30f;
                if (c0 + 1 > rloc + 8) s[nt][3] = -1e30f;
            }
        }

        float t0 = -1e30f, t1 = -1e30f;
#pragma unroll
        for (int nt = 0; nt < 8; nt++) {
            t0 = fmaxf(t0, fmaxf(s[nt][0], s[nt][1]));
            t1 = fmaxf(t1, fmaxf(s[nt][2], s[nt][3]));
        }
        t0 = fmaxf(t0, __shfl_xor_sync(0xffffffffu, t0, 1));
        t0 = fmaxf(t0, __shfl_xor_sync(0xffffffffu, t0, 2));
        t1 = fmaxf(t1, __shfl_xor_sync(0xffffffffu, t1, 1));
        t1 = fmaxf(t1, __shfl_xor_sync(0xffffffffu, t1, 2));
        float mn0 = fmaxf(m0, t0), mn1 = fmaxf(m1, t1);
        float sc0 = exp2f((m0 - mn0) * SC), sc1 = exp2f((m1 - mn1) * SC);
        m0 = mn0; m1 = mn1;

        float rs0 = 0.f, rs1 = 0.f;
#pragma unroll
        for (int nt = 0; nt < 8; nt++) {
            float p0 = exp2f((s[nt][0] - m0) * SC);
            float p1 = exp2f((s[nt][1] - m0) * SC);
            float p2 = exp2f((s[nt][2] - m1) * SC);
            float p3 = exp2f((s[nt][3] - m1) * SC);
            rs0 += p0 + p1; rs1 += p2 + p3;
            int c0 = nt * 8 + 2 * (lane & 3);
            Ps[rloc * AST + c0]           = f2tf(p0);
            Ps[rloc * AST + c0 + 1]       = f2tf(p1);
            Ps[(rloc + 8) * AST + c0]     = f2tf(p2);
            Ps[(rloc + 8) * AST + c0 + 1] = f2tf(p3);
        }
        rs0 += __shfl_xor_sync(0xffffffffu, rs0, 1);
        rs0 += __shfl_xor_sync(0xffffffffu, rs0, 2);
        rs1 += __shfl_xor_sync(0xffffffffu, rs1, 1);
        rs1 += __shfl_xor_sync(0xffffffffu, rs1, 2);
        l0 = l0 * sc0 + rs0; l1 = l1 * sc1 + rs1;

#pragma unroll
        for (int nt = 0; nt < 8; nt++) {
            o[nt][0] *= sc0; o[nt][1] *= sc0; o[nt][2] *= sc1; o[nt][3] *= sc1;
        }
        __syncwarp();

#pragma unroll
        for (int kc = 0; kc < 8; kc++) {
            int kb = kc * 8 + (lane & 3);
            uint32_t af[4];
            af[0] = Ps[rloc * AST + kb];
            af[1] = Ps[(rloc + 8) * AST + kb];
            af[2] = Ps[rloc * AST + kb + 4];
            af[3] = Ps[(rloc + 8) * AST + kb + 4];
#pragma unroll
            for (int nt = 0; nt < 8; nt++) {
                int cc = nt * 8 + (lane >> 2);
                uint32_t bf[2] = { Vs[kb * AST + cc], Vs[(kb + 4) * AST + cc] };
                mma_tf32(o[nt], af, bf);
            }
        }
    }

    float inv0 = 1.f / l0, inv1 = 1.f / l1;
    int grow = qt * BQ + rloc;
#pragma unroll
    for (int nt = 0; nt < 8; nt++) {
        int c0 = nt * 8 + 2 * (lane & 3);
        *(float2*)(Y + base + (size_t)grow * DD + c0)       = make_float2(o[nt][0] * inv0, o[nt][1] * inv0);
        *(float2*)(Y + base + (size_t)(grow + 8) * DD + c0) = make_float2(o[nt][2] * inv1, o[nt][3] * inv1);
    }
}

// ---------------- launcher ----------------
extern "C" void kernel_launch(void* const* d_in, const int* in_sizes, int n_in,
                              void* d_out, int out_size) {
    const float* states  = (const float*)d_in[0];
    const int*   actions = (const int*)  d_in[1];
    const float* rtg     = (const float*)d_in[2];
    const int*   tsteps  = (const int*)  d_in[3];
    const float* pos_emb = (const float*)d_in[4];
    const float* gpe     = (const float*)d_in[5];
    const float* Ws      = (const float*)d_in[6];
    const float* bs      = (const float*)d_in[7];
    const float* Wr      = (const float*)d_in[8];
    const float* br      = (const float*)d_in[9];
    const float* aemb    = (const float*)d_in[10];
    const float* ln1_g   = (const float*)d_in[11];
    const float* ln1_b   = (const float*)d_in[12];
    const float* Wq      = (const float*)d_in[13];
    const float* bq      = (const float*)d_in[14];
    const float* Wk      = (const float*)d_in[15];
    const float* bk      = (const float*)d_in[16];
    const float* Wv      = (const float*)d_in[17];
    const float* bv      = (const float*)d_in[18];
    const float* Wo      = (const float*)d_in[19];
    const float* bo      = (const float*)d_in[20];
    const float* ln2_g   = (const float*)d_in[21];
    const float* ln2_b   = (const float*)d_in[22];
    const float* W1      = (const float*)d_in[23];
    const float* b1      = (const float*)d_in[24];
    const float* W2      = (const float*)d_in[25];
    const float* b2      = (const float*)d_in[26];
    const float* lnf_g   = (const float*)d_in[27];
    const float* lnf_b   = (const float*)d_in[28];
    const float* head_W  = (const float*)d_in[29];

    float *x, *hb, *qb, *kb, *vb, *yb, *ffb;
    cudaGetSymbolAddress((void**)&x,  g_x);
    cudaGetSymbolAddress((void**)&hb, g_h);
    cudaGetSymbolAddress((void**)&qb, g_q);
    cudaGetSymbolAddress((void**)&kb, g_k);
    cudaGetSymbolAddress((void**)&vb, g_v);
    cudaGetSymbolAddress((void**)&yb, g_y);
    cudaGetSymbolAddress((void**)&ffb, g_ff);

    cudaFuncSetAttribute(flash_attn, cudaFuncAttributeMaxDynamicSharedMemorySize, ATTN_SMEM);

    embed_kernel<<<dim3(MP, BB), 256>>>(states, actions, rtg, tsteps,
                                        pos_emb, gpe, Ws, bs, Wr, br, aemb);

    for (int l = 0; l < LL; ++l) {
        size_t wOff = (size_t)l * DD * DD;
        size_t bOff = (size_t)l * DD;
        ln_kernel<<<ROWS, 256>>>(x, ln1_g + bOff, ln1_b + bOff, hb);
        qkv_tc<<<dim3(DD / BNT, ROWS / BMT, 3), 256>>>(hb,
            Wq + wOff, bq + bOff, qb,
            Wk + wOff, bk + bOff, kb,
            Wv + wOff, bv + bOff, vb);
        flash_attn<<<dim3(MP / BQ, BB * HH), 128, ATTN_SMEM>>>(qb, kb, vb, yb);
        gemm_tc<2><<<dim3(DD / BNT, ROWS / BMT), 256>>>(yb, Wo + wOff, bo + bOff, x, x, DD, DD);
        ln_kernel<<<ROWS, 256>>>(x, ln2_g + bOff, ln2_b + bOff, hb);
        gemm_tc<1><<<dim3(FFD / BNT, ROWS / BMT), 256>>>(hb, W1 + (size_t)l * FFD * DD,
                                                         b1 + (size_t)l * FFD, ffb, nullptr, DD, FFD);
        gemm_tc<2><<<dim3(DD / BNT, ROWS / BMT), 256>>>(ffb, W2 + (size_t)l * DD * FFD,
                                                        b2 + bOff, x, x, FFD, DD);
    }

    gather_ln_kernel<<<BB * TSZ, 256>>>(x, lnf_g, lnf_b, hb);
    gemm_tc<0><<<dim3(VV / BNT, (BB * TSZ) / BMT), 256>>>(hb, head_W, nullptr,
                                                          (float*)d_out, nullptr, DD, VV);
}

// round 11
// speedup vs baseline: 7.2618x; 1.9699x over previous
#include <cuda_runtime.h>
#include <cuda_fp16.h>
#include <math.h>
#include <stdint.h>

#define BB   4
#define TSZ  256
#define DD   1024
#define HH   16
#define DHH  64
#define LL   4
#define VV   32000
#define FFD  4096
#define MM   767
#define MP   768
#define ROWS (BB*MP)   /* 3072 */

// fp16 GEMM: 128x128 tile, K-chunk 32, 4-stage cp.async ring
#define SH      40                     /* smem stride in halves (32 data + 8 pad) */
#define STG_H   (128*SH)               /* halves per operand per stage = 5120 */
#define STG_B   (2*STG_H*2)            /* stage bytes: A+B = 20480 */
#define GEMM_SMEM (4*STG_B)            /* 81920 */

// attention: 64x64 tiles, fp16 smem stride 72 halves
#define BQ  64
#define BK  64
#define ASH 72

// ---------------- scratch ----------------
__device__ float  g_x [ROWS*DD];
__device__ __half g_h [ROWS*DD];
__device__ __half g_q [ROWS*DD];
__device__ __half g_k [ROWS*DD];
__device__ __half g_v [ROWS*DD];
__device__ __half g_y [ROWS*DD];
__device__ __half g_ff[ROWS*FFD];
#define HOFF_WQ 0
#define HOFF_WK 4194304
#define HOFF_WV 8388608
#define HOFF_WO 12582912
#define HOFF_W1 16777216
#define HOFF_W2 33554432
#define HOFF_HD 50331648
__device__ __half g_wh[83099648];

// ---------------- PTX helpers ----------------
__device__ __forceinline__ uint32_t smem_u32(const void* p) {
    uint32_t a;
    asm("{ .reg .u64 t; cvta.to.shared.u64 t, %1; cvt.u32.u64 %0, t; }" : "=r"(a) : "l"(p));
    return a;
}
__device__ __forceinline__ void cp16(uint32_t dst, const void* src) {
    asm volatile("cp.async.cg.shared.global [%0], [%1], 16;" :: "r"(dst), "l"(src));
}
#define CP_COMMIT() asm volatile("cp.async.commit_group;" ::: "memory")
#define CP_WAIT2()  asm volatile("cp.async.wait_group 2;" ::: "memory")
#define CP_WAIT1()  asm volatile("cp.async.wait_group 1;" ::: "memory")
#define CP_WAIT0()  asm volatile("cp.async.wait_group 0;" ::: "memory")

__device__ __forceinline__ void ldm_x4(uint32_t& r0, uint32_t& r1, uint32_t& r2, uint32_t& r3,
                                       uint32_t addr) {
    asm volatile("ldmatrix.sync.aligned.m8n8.x4.shared.b16 {%0,%1,%2,%3}, [%4];"
        : "=r"(r0), "=r"(r1), "=r"(r2), "=r"(r3) : "r"(addr));
}
__device__ __forceinline__ void ldm_x4t(uint32_t& r0, uint32_t& r1, uint32_t& r2, uint32_t& r3,
                                        uint32_t addr) {
    asm volatile("ldmatrix.sync.aligned.m8n8.x4.trans.shared.b16 {%0,%1,%2,%3}, [%4];"
        : "=r"(r0), "=r"(r1), "=r"(r2), "=r"(r3) : "r"(addr));
}
__device__ __forceinline__ void mma_f16(float* c, const uint32_t* a, const uint32_t* b) {
    asm volatile(
        "mma.sync.aligned.m16n8k16.row.col.f32.f16.f16.f32 "
        "{%0,%1,%2,%3},{%4,%5,%6,%7},{%8,%9},{%0,%1,%2,%3};"
        : "+f"(c[0]), "+f"(c[1]), "+f"(c[2]), "+f"(c[3])
        : "r"(a[0]), "r"(a[1]), "r"(a[2]), "r"(a[3]), "r"(b[0]), "r"(b[1]));
}
__device__ __forceinline__ uint32_t f2h2(float x, float y) {
    __half2 h = __floats2half2_rn(x, y);
    return *(uint32_t*)&h;
}
__device__ __forceinline__ void store2(float* p, float a, float b) {
    *(float2*)p = make_float2(a, b);
}
__device__ __forceinline__ void store2(__half* p, float a, float b) {
    *(__half2*)p = __floats2half2_rn(a, b);
}

// ---------------- helpers ----------------
__device__ __forceinline__ float blk_sum(float v, float* sh) {
    int lane = threadIdx.x & 31, w = threadIdx.x >> 5;
#pragma unroll
    for (int o = 16; o; o >>= 1) v += __shfl_down_sync(0xffffffffu, v, o);
    if (lane == 0) sh[w] = v;
    __syncthreads();
    if (w == 0) {
        float t = (lane < (int)(blockDim.x >> 5)) ? sh[lane] : 0.f;
#pragma unroll
        for (int o = 16; o; o >>= 1) t += __shfl_down_sync(0xffffffffu, t, o);
        if (lane == 0) sh[0] = t;
    }
    __syncthreads();
    float r = sh[0];
    __syncthreads();
    return r;
}

// ---------------- fp32 -> fp16 convert (weights) ----------------
__global__ void cvt_h(const float* __restrict__ src, __half* __restrict__ dst, int n8) {
    int i = blockIdx.x * 256 + threadIdx.x;
    if (i < n8) {
        float4 v0 = ((const float4*)src)[2 * i];
        float4 v1 = ((const float4*)src)[2 * i + 1];
        uint4 o;
        o.x = f2h2(v0.x, v0.y); o.y = f2h2(v0.z, v0.w);
        o.z = f2h2(v1.x, v1.y); o.w = f2h2(v1.z, v1.w);
        ((uint4*)dst)[i] = o;
    }
}

// ---------------- embedding (fp32 residual stream) ----------------
__global__ void embed_kernel(const float* __restrict__ states,
                             const int*   __restrict__ actions,
                             const float* __restrict__ rtg,
                             const int*   __restrict__ timesteps,
                             const float* __restrict__ pos_emb,
                             const float* __restrict__ gpe,
                             const float* __restrict__ Ws, const float* __restrict__ bs,
                             const float* __restrict__ Wr, const float* __restrict__ br,
                             const float* __restrict__ aemb) {
    int m = blockIdx.x;
    int b = blockIdx.y;
    float* out = g_x + ((size_t)(b * MP + m)) * DD;
    if (m >= MM) {
        for (int d = threadIdx.x; d < DD; d += blockDim.x) out[d] = 0.f;
        return;
    }
    int ts = timesteps[b];
    int r = m % 3, t = m / 3;
    float sv = 0.f; int ai = 0;
    if (r == 0) sv = rtg[b * TSZ + t];
    else if (r == 1) sv = states[b * TSZ + t];
    else ai = actions[b * TSZ + t + 1];
    for (int d = threadIdx.x; d < DD; d += blockDim.x) {
        float tok;
        if (r == 0)      tok = tanhf(sv * Wr[d] + br[d]);
        else if (r == 1) tok = tanhf(sv * Ws[d] + bs[d]);
        else             tok = tanhf(aemb[(size_t)ai * DD + d]);
        out[d] = tok + gpe[(size_t)ts * DD + d] + pos_emb[(size_t)m * DD + d];
    }
}

// ---------------- layernorm: fp32 in -> fp16 out ----------------
__device__ __forceinline__ void ln_row(const float* __restrict__ xin,
                                       const float* __restrict__ g,
                                       const float* __restrict__ b,
                                       __half* __restrict__ yout,
                                       float* red) {
    int t = threadIdx.x;
    float4 v = ((const float4*)xin)[t];
    float s  = v.x + v.y + v.z + v.w;
    float ss = v.x * v.x + v.y * v.y + v.z * v.z + v.w * v.w;
    float mean = blk_sum(s, red) * (1.f / DD);
    float var  = blk_sum(ss, red) * (1.f / DD) - mean * mean;
    float rs = rsqrtf(var + 1e-5f);
    float4 gg = ((const float4*)g)[t];
    float4 bb = ((const float4*)b)[t];
    uint2 o;
    o.x = f2h2((v.x - mean) * rs * gg.x + bb.x, (v.y - mean) * rs * gg.y + bb.y);
    o.y = f2h2((v.z - mean) * rs * gg.z + bb.z, (v.w - mean) * rs * gg.w + bb.w);
    *(uint2*)(yout + 4 * t) = o;
}

__global__ void ln_kernel(const float* __restrict__ in,
                          const float* __restrict__ g,
                          const float* __restrict__ b,
                          __half* __restrict__ out) {
    __shared__ float red[32];
    size_t row = blockIdx.x;
    ln_row(in + row * DD, g, b, out + row * DD, red);
}

__global__ void gather_ln_kernel(const float* __restrict__ in,
                                 const float* __restrict__ g,
                                 const float* __restrict__ b,
                                 __half* __restrict__ out) {
    __shared__ float red[32];
    int i = blockIdx.x;
    int bb = i >> 8, t = i & 255;
    size_t row = (size_t)bb * MP + 1 + 3 * t;
    ln_row(in + row * DD, g, b, out + (size_t)i * DD, red);
}

// ---------------- fp16 tensor-core GEMM: C[rows,N] = A[rows,K] @ W[N,K]^T ----------------
__device__ __forceinline__ void load_stage(const __half* __restrict__ Ab,
                                           const __half* __restrict__ Wb,
                                           int K, int k0, uint32_t stage, int tid) {
#pragma unroll
    for (int i = 0; i < 4; i++) {
        int idx = tid + 256 * i;                 // 0..1023
        int isB = idx >> 9;                      // 0: A, 1: B
        int j = idx & 511;
        int r = j >> 2, u = j & 3;               // row 0..127, 16B-unit 0..3
        const __half* src = (isB ? Wb : Ab) + (size_t)r * K + k0 + u * 8;
        uint32_t dst = stage + (uint32_t)isB * (STG_H * 2) + (uint32_t)(r * SH + u * 8) * 2;
        cp16(dst, src);
    }
    CP_COMMIT();
}

template <int EPI, typename TO>
__device__ void gemm_body(const __half* __restrict__ A, const __half* __restrict__ W,
                          const float* __restrict__ bias, TO* __restrict__ C,
                          const float* __restrict__ res, int K, int N, int bx, int by) {
    extern __shared__ char dyn[];
    uint32_t base = smem_u32(dyn);
    int tid = threadIdx.x, lane = tid & 31, warp = tid >> 5;
    int warpM = (warp & 1) * 64;
    int warpN = (warp >> 1) * 32;
    int rowBase = by * 128, colBase = bx * 128;
    const __half* Ab = A + (size_t)rowBase * K;
    const __half* Wb = W + (size_t)colBase * K;
    int nc = K / 32;

    float acc[4][4][4];
#pragma unroll
    for (int i = 0; i < 4; i++)
#pragma unroll
        for (int j = 0; j < 4; j++)
#pragma unroll
            for (int q = 0; q < 4; q++) acc[i][j][q] = 0.f;

    load_stage(Ab, Wb, K, 0,  base,             tid);
    load_stage(Ab, Wb, K, 32, base + STG_B,     tid);
    load_stage(Ab, Wb, K, 64, base + 2 * STG_B, tid);

    int lrow = lane & 15, lhi = (lane >> 4) * 8;
    for (int c = 0; c < nc; c++) {
        if (c + 2 < nc)      { CP_WAIT2(); }
        else if (c + 1 < nc) { CP_WAIT1(); }
        else                 { CP_WAIT0(); }
        __syncthreads();
        uint32_t as  = base + (uint32_t)(c & 3) * STG_B;
        uint32_t bs_ = as + STG_H * 2;
#pragma unroll
        for (int ks = 0; ks < 2; ks++) {
            uint32_t af[4][4], bf[4][2];
#pragma unroll
            for (int mt = 0; mt < 4; mt++) {
                uint32_t addr = as + (uint32_t)(((warpM + mt * 16 + lrow) * SH) + ks * 16 + lhi) * 2;
                ldm_x4(af[mt][0], af[mt][1], af[mt][2], af[mt][3], addr);
            }
#pragma unroll
            for (int np = 0; np < 2; np++) {
                uint32_t r0, r1, r2, r3;
                uint32_t addr = bs_ + (uint32_t)(((warpN + np * 16 + lrow) * SH) + ks * 16 + lhi) * 2;
                ldm_x4(r0, r1, r2, r3, addr);
                bf[2 * np][0] = r0; bf[2 * np][1] = r2;
                bf[2 * np + 1][0] = r1; bf[2 * np + 1][1] = r3;
            }
#pragma unroll
            for (int mt = 0; mt < 4; mt++)
#pragma unroll
                for (int nt = 0; nt < 4; nt++)
                    mma_f16(acc[mt][nt], af[mt], bf[nt]);
        }
        if (c + 3 < nc) load_stage(Ab, Wb, K, (c + 3) * 32, base + (uint32_t)((c + 3) & 3) * STG_B, tid);
    }

    // epilogue
#pragma unroll
    for (int nt = 0; nt < 4; ++nt) {
        int col = colBase + warpN + nt * 8 + 2 * (lane & 3);
        float bv0 = 0.f, bv1 = 0.f;
        if (bias) { bv0 = bias[col]; bv1 = bias[col + 1]; }
#pragma unroll
        for (int mt = 0; mt < 4; ++mt) {
#pragma unroll
            for (int hf = 0; hf < 2; ++hf) {
                int row = rowBase + warpM + mt * 16 + (lane >> 2) + hf * 8;
                float v0 = acc[mt][nt][hf * 2 + 0] + bv0;
                float v1 = acc[mt][nt][hf * 2 + 1] + bv1;
                if (EPI == 1) {
                    v0 = 0.5f * v0 * (1.f + erff(v0 * 0.70710678118654752f));
                    v1 = 0.5f * v1 * (1.f + erff(v1 * 0.70710678118654752f));
                } else if (EPI == 2) {
                    const float* rr = res + (size_t)row * N + col;
                    v0 += rr[0]; v1 += rr[1];
                }
                store2(C + (size_t)row * N + col, v0, v1);
            }
        }
    }
}

template <int EPI, typename TO>
__global__ void __launch_bounds__(256)
gemm_tc(const __half* __restrict__ A, const __half* __restrict__ W,
        const float* __restrict__ bias, TO* __restrict__ C,
        const float* __restrict__ res, int K, int N) {
    gemm_body<EPI, TO>(A, W, bias, C, res, K, N, blockIdx.x, blockIdx.y);
}

__global__ void __launch_bounds__(256)
qkv_tc(const __half* __restrict__ A,
       const __half* Wq, const float* bq, __half* Cq,
       const __half* Wk, const float* bk, __half* Ck,
       const __half* Wv, const float* bv, __half* Cv) {
    const __half* W; const float* b; __half* C;
    if (blockIdx.z == 0)      { W = Wq; b = bq; C = Cq; }
    else if (blockIdx.z == 1) { W = Wk; b = bk; C = Ck; }
    else                      { W = Wv; b = bv; C = Cv; }
    gemm_body<0, __half>(A, W, b, C, nullptr, DD, DD, blockIdx.x, blockIdx.y);
}

// ---------------- flash attention: fp16 mma, P kept in registers ----------------
__global__ void __launch_bounds__(128)
flash_attn(const __half* __restrict__ Qg, const __half* __restrict__ Kg,
           const __half* __restrict__ Vg, __half* __restrict__ Y) {
    int qt = gridDim.x - 1 - blockIdx.x;   // heavy tiles first
    int bh = blockIdx.y;
    int b = bh >> 4, h = bh & 15;
    __shared__ __half Qs[BQ * ASH];
    __shared__ __half Ks[BK * ASH];
    __shared__ __half Vs[BK * ASH];
    int tid = threadIdx.x, lane = tid & 31, warp = tid >> 5;
    size_t gbase = (size_t)b * MP * DD + (size_t)h * DHH;
    uint32_t qb_s = smem_u32(Qs), kb_s = smem_u32(Ks), vb_s = smem_u32(Vs);

#pragma unroll
    for (int i = 0; i < 4; i++) {
        int idx = tid + 128 * i;
        int r = idx >> 3, u = idx & 7;
        *(uint4*)(Qs + r * ASH + u * 8) =
            *(const uint4*)(Qg + gbase + (size_t)(qt * BQ + r) * DD + u * 8);
    }

    const float SC = 0.125f * 1.4426950408889634f;
    float m0 = -1e30f, m1 = -1e30f, l0 = 0.f, l1 = 0.f;
    float o[8][4];
#pragma unroll
    for (int nt = 0; nt < 8; nt++) { o[nt][0] = o[nt][1] = o[nt][2] = o[nt][3] = 0.f; }
    int rloc = warp * 16 + (lane >> 2);
    int lrow = lane & 15, lhi = (lane >> 4) * 8;

    for (int kt = 0; kt <= qt; kt++) {
        __syncthreads();
#pragma unroll
        for (int i = 0; i < 4; i++) {
            int idx = tid + 128 * i;
            int r = idx >> 3, u = idx & 7;
            const __half* ks = Kg + gbase + (size_t)(kt * BK + r) * DD + u * 8;
            const __half* vs = Vg + gbase + (size_t)(kt * BK + r) * DD + u * 8;
            *(uint4*)(Ks + r * ASH + u * 8) = *(const uint4*)ks;
            *(uint4*)(Vs + r * ASH + u * 8) = *(const uint4*)vs;
        }
        __syncthreads();

        float s[8][4];
#pragma unroll
        for (int nt = 0; nt < 8; nt++) { s[nt][0] = s[nt][1] = s[nt][2] = s[nt][3] = 0.f; }
#pragma unroll
        for (int kc = 0; kc < 4; kc++) {
            uint32_t af[4];
            ldm_x4(af[0], af[1], af[2], af[3],
                   qb_s + (uint32_t)(((warp * 16 + lrow) * ASH) + kc * 16 + lhi) * 2);
#pragma unroll
            for (int np = 0; np < 4; np++) {
                uint32_t r0, r1, r2, r3;
                ldm_x4(r0, r1, r2, r3,
                       kb_s + (uint32_t)(((np * 16 + lrow) * ASH) + kc * 16 + lhi) * 2);
                uint32_t b0[2] = { r0, r2 }, b1[2] = { r1, r3 };
                mma_f16(s[2 * np],     af, b0);
                mma_f16(s[2 * np + 1], af, b1);
            }
        }

        if (kt == qt) {
#pragma unroll
            for (int nt = 0; nt < 8; nt++) {
                int c0 = nt * 8 + 2 * (lane & 3);
                if (c0     > rloc)     s[nt][0] = -1e30f;
                if (c0 + 1 > rloc)     s[nt][1] = -1e30f;
                if (c0     > rloc + 8) s[nt][2] = -1e30f;
                if (c0 + 1 > rloc + 8) s[nt][3] = -1e30f;
            }
        }

        float t0 = -1e30f, t1 = -1e30f;
#pragma unroll
        for (int nt = 0; nt < 8; nt++) {
            t0 = fmaxf(t0, fmaxf(s[nt][0], s[nt][1]));
            t1 = fmaxf(t1, fmaxf(s[nt][2], s[nt][3]));
        }
        t0 = fmaxf(t0, __shfl_xor_sync(0xffffffffu, t0, 1));
        t0 = fmaxf(t0, __shfl_xor_sync(0xffffffffu, t0, 2));
        t1 = fmaxf(t1, __shfl_xor_sync(0xffffffffu, t1, 1));
        t1 = fmaxf(t1, __shfl_xor_sync(0xffffffffu, t1, 2));
        float mn0 = fmaxf(m0, t0), mn1 = fmaxf(m1, t1);
        float sc0 = exp2f((m0 - mn0) * SC), sc1 = exp2f((m1 - mn1) * SC);
        m0 = mn0; m1 = mn1;

        float rs0 = 0.f, rs1 = 0.f;
#pragma unroll
        for (int nt = 0; nt < 8; nt++) {
            s[nt][0] = exp2f((s[nt][0] - m0) * SC);
            s[nt][1] = exp2f((s[nt][1] - m0) * SC);
            s[nt][2] = exp2f((s[nt][2] - m1) * SC);
            s[nt][3] = exp2f((s[nt][3] - m1) * SC);
            rs0 += s[nt][0] + s[nt][1]; rs1 += s[nt][2] + s[nt][3];
        }
        rs0 += __shfl_xor_sync(0xffffffffu, rs0, 1);
        rs0 += __shfl_xor_sync(0xffffffffu, rs0, 2);
        rs1 += __shfl_xor_sync(0xffffffffu, rs1, 1);
        rs1 += __shfl_xor_sync(0xffffffffu, rs1, 2);
        l0 = l0 * sc0 + rs0; l1 = l1 * sc1 + rs1;

#pragma unroll
        for (int nt = 0; nt < 8; nt++) {
            o[nt][0] *= sc0; o[nt][1] *= sc0; o[nt][2] *= sc1; o[nt][3] *= sc1;
        }

#pragma unroll
        for (int kc = 0; kc < 4; kc++) {
            uint32_t af[4];
            af[0] = f2h2(s[2 * kc][0],     s[2 * kc][1]);
            af[1] = f2h2(s[2 * kc][2],     s[2 * kc][3]);
            af[2] = f2h2(s[2 * kc + 1][0], s[2 * kc + 1][1]);
            af[3] = f2h2(s[2 * kc + 1][2], s[2 * kc + 1][3]);
#pragma unroll
            for (int np = 0; np < 4; np++) {
                uint32_t r0, r1, r2, r3;
                ldm_x4t(r0, r1, r2, r3,
                        vb_s + (uint32_t)(((kc * 16 + lrow) * ASH) + np * 16 + lhi) * 2);
                uint32_t b0[2] = { r0, r1 }, b1[2] = { r2, r3 };
                mma_f16(o[2 * np],     af, b0);
                mma_f16(o[2 * np + 1], af, b1);
            }
        }
    }

    float inv0 = 1.f / l0, inv1 = 1.f / l1;
    int grow = qt * BQ + rloc;
#pragma unroll
    for (int nt = 0; nt < 8; nt++) {
        int c0 = nt * 8 + 2 * (lane & 3);
        *(uint32_t*)(Y + gbase + (size_t)grow * DD + c0)       = f2h2(o[nt][0] * inv0, o[nt][1] * inv0);
        *(uint32_t*)(Y + gbase + (size_t)(grow + 8) * DD + c0) = f2h2(o[nt][2] * inv1, o[nt][3] * inv1);
    }
}

// ---------------- launcher ----------------
extern "C" void kernel_launch(void* const* d_in, const int* in_sizes, int n_in,
                              void* d_out, int out_size) {
    const float* states  = (const float*)d_in[0];
    const int*   actions = (const int*)  d_in[1];
    const float* rtg     = (const float*)d_in[2];
    const int*   tsteps  = (const int*)  d_in[3];
    const float* pos_emb = (const float*)d_in[4];
    const float* gpe     = (const float*)d_in[5];
    const float* Ws      = (const float*)d_in[6];
    const float* bs      = (const float*)d_in[7];
    const float* Wr      = (const float*)d_in[8];
    const float* br      = (const float*)d_in[9];
    const float* aemb    = (const float*)d_in[10];
    const float* ln1_g   = (const float*)d_in[11];
    const float* ln1_b   = (const float*)d_in[12];
    const float* Wq      = (const float*)d_in[13];
    const float* bq      = (const float*)d_in[14];
    const float* Wk      = (const float*)d_in[15];
    const float* bk      = (const float*)d_in[16];
    const float* Wv      = (const float*)d_in[17];
    const float* bv      = (const float*)d_in[18];
    const float* Wo      = (const float*)d_in[19];
    const float* bo      = (const float*)d_in[20];
    const float* ln2_g   = (const float*)d_in[21];
    const float* ln2_b   = (const float*)d_in[22];
    const float* W1      = (const float*)d_in[23];
    const float* b1      = (const float*)d_in[24];
    const float* W2      = (const float*)d_in[25];
    const float* b2      = (const float*)d_in[26];
    const float* lnf_g   = (const float*)d_in[27];
    const float* lnf_b   = (const float*)d_in[28];
    const float* head_W  = (const float*)d_in[29];

    float* x; __half *hb, *qb, *kb, *vb, *yb, *ffb, *wh;
    cudaGetSymbolAddress((void**)&x,  g_x);
    cudaGetSymbolAddress((void**)&hb, g_h);
    cudaGetSymbolAddress((void**)&qb, g_q);
    cudaGetSymbolAddress((void**)&kb, g_k);
    cudaGetSymbolAddress((void**)&vb, g_v);
    cudaGetSymbolAddress((void**)&yb, g_y);
    cudaGetSymbolAddress((void**)&ffb, g_ff);
    cudaGetSymbolAddress((void**)&wh, g_wh);

    cudaFuncSetAttribute(gemm_tc<0, float>,  cudaFuncAttributeMaxDynamicSharedMemorySize, GEMM_SMEM);
    cudaFuncSetAttribute(gemm_tc<1, __half>, cudaFuncAttributeMaxDynamicSharedMemorySize, GEMM_SMEM);
    cudaFuncSetAttribute(gemm_tc<2, float>,  cudaFuncAttributeMaxDynamicSharedMemorySize, GEMM_SMEM);
    cudaFuncSetAttribute(qkv_tc,             cudaFuncAttributeMaxDynamicSharedMemorySize, GEMM_SMEM);

    cvt_h<<<(4194304/8 + 255)/256, 256>>>(Wq, wh + HOFF_WQ, 4194304/8);
    cvt_h<<<(4194304/8 + 255)/256, 256>>>(Wk, wh + HOFF_WK, 4194304/8);
    cvt_h<<<(4194304/8 + 255)/256, 256>>>(Wv, wh + HOFF_WV, 4194304/8);
    cvt_h<<<(4194304/8 + 255)/256, 256>>>(Wo, wh + HOFF_WO, 4194304/8);
    cvt_h<<<(16777216/8 + 255)/256, 256>>>(W1, wh + HOFF_W1, 16777216/8);
    cvt_h<<<(16777216/8 + 255)/256, 256>>>(W2, wh + HOFF_W2, 16777216/8);
    cvt_h<<<(32768000/8 + 255)/256, 256>>>(head_W, wh + HOFF_HD, 32768000/8);

    embed_kernel<<<dim3(MP, BB), 256>>>(states, actions, rtg, tsteps,
                                        pos_emb, gpe, Ws, bs, Wr, br, aemb);

    for (int l = 0; l < LL; ++l) {
        size_t bOff = (size_t)l * DD;
        const __half* wq_l = wh + HOFF_WQ + (size_t)l * DD * DD;
        const __half* wk_l = wh + HOFF_WK + (size_t)l * DD * DD;
        const __half* wv_l = wh + HOFF_WV + (size_t)l * DD * DD;
        const __half* wo_l = wh + HOFF_WO + (size_t)l * DD * DD;
        const __half* w1_l = wh + HOFF_W1 + (size_t)l * FFD * DD;
        const __half* w2_l = wh + HOFF_W2 + (size_t)l * DD * FFD;

        ln_kernel<<<ROWS, 256>>>(x, ln1_g + bOff, ln1_b + bOff, hb);
        qkv_tc<<<dim3(DD/128, ROWS/128, 3), 256, GEMM_SMEM>>>(hb,
            wq_l, bq + bOff, qb, wk_l, bk + bOff, kb, wv_l, bv + bOff, vb);
        flash_attn<<<dim3(MP / BQ, BB * HH), 128>>>(qb, kb, vb, yb);
        gemm_tc<2, float><<<dim3(DD/128, ROWS/128), 256, GEMM_SMEM>>>(yb, wo_l, bo + bOff, x, x, DD, DD);
        ln_kernel<<<ROWS, 256>>>(x, ln2_g + bOff, ln2_b + bOff, hb);
        gemm_tc<1, __half><<<dim3(FFD/128, ROWS/128), 256, GEMM_SMEM>>>(hb, w1_l, b1 + (size_t)l * FFD,
                                                                        ffb, nullptr, DD, FFD);
        gemm_tc<2, float><<<dim3(DD/128, ROWS/128), 256, GEMM_SMEM>>>(ffb, w2_l, b2 + bOff, x, x, FFD, DD);
    }

    gather_ln_kernel<<<BB * TSZ, 256>>>(x, lnf_g, lnf_b, hb);
    gemm_tc<0, float><<<dim3(VV/128, (BB * TSZ)/128), 256, GEMM_SMEM>>>(hb, wh + HOFF_HD, nullptr,
                                                                        (float*)d_out, nullptr, DD, VV);
}